// round 1
// baseline (speedup 1.0000x reference)
#include <cuda_runtime.h>
#include <cuda_bf16.h>
#include <math.h>

#define B_     2
#define S_     32
#define BS_    64
#define C_     128
#define HGT    24
#define WID    24
#define L_     576
#define HEADS_ 2
#define QKD_   64
#define VD_    128
#define HID_   256
#define OUTC_  128

// ---------------- scratch (static device globals; no allocation) ----------------
__device__ float g_bias[HEADS_ * L_ * L_];            // (head, i, j)
__device__ float g_q[BS_ * HEADS_ * QKD_ * L_];       // (bs,head,d,l)  d-major
__device__ float g_k[BS_ * HEADS_ * QKD_ * L_];
__device__ float g_v[BS_ * HEADS_ * VD_ * L_];        // (bs,head,d,l)
__device__ float g_att[BS_ * L_ * HID_];              // (bs,l,ch) position-major

// ---------------- kernel 1: continuous relative position bias ----------------
__global__ void cpb_bias_kernel(const float* __restrict__ w1,
                                const float* __restrict__ b1,
                                const float* __restrict__ w2) {
    __shared__ float s_w1[256];
    __shared__ float s_b1[128];
    __shared__ float s_w2[256];
    int tid = threadIdx.x;
    s_w1[tid] = w1[tid];          // (128,2) flat
    if (tid < 128) s_b1[tid] = b1[tid];
    s_w2[tid] = w2[tid];          // (2,128) flat
    __syncthreads();

    int idx = blockIdx.x * 256 + tid;      // < 576*576
    int i = idx / L_, j = idx % L_;
    int yi = i / WID, xi = i % WID;
    int yj = j / WID, xj = j % WID;
    float ry = (float)(yi - yj) * (8.0f / 23.0f);
    float rx = (float)(xi - xj) * (8.0f / 23.0f);
    ry = copysignf(log2f(1.0f + fabsf(ry)) * (1.0f / 3.0f), ry);
    rx = copysignf(log2f(1.0f + fabsf(rx)) * (1.0f / 3.0f), rx);

    float acc0 = 0.f, acc1 = 0.f;
    #pragma unroll 4
    for (int k = 0; k < 128; k++) {
        float h = fmaxf(0.f, ry * s_w1[2 * k] + rx * s_w1[2 * k + 1] + s_b1[k]);
        acc0 += h * s_w2[k];
        acc1 += h * s_w2[128 + k];
    }
    g_bias[idx] = acc0;
    g_bias[L_ * L_ + idx] = acc1;
}

// ---------------- kernel 2: QKV projection (512x128 @ 128x576 per bs) ----------------
// Block: (bs, l-tile of 64). smem: xs[128][64], ws[128][65] (k-major transposed W tile).
__global__ void qkv_kernel(const float* __restrict__ x,
                           const float* __restrict__ qk_w,
                           const float* __restrict__ v_w) {
    int bs = blockIdx.y;
    int l0 = blockIdx.x * 64;
    extern __shared__ float sm[];
    float* xs = sm;                 // [128][64]
    float* ws = sm + 128 * 64;      // [128][65]

    const float* xb = x + (size_t)bs * C_ * L_;
    for (int idx = threadIdx.x; idx < 128 * 16; idx += 256) {
        int c = idx >> 4, lv = idx & 15;
        float4 v4 = *(const float4*)(xb + (size_t)c * L_ + l0 + lv * 4);
        *(float4*)(xs + c * 64 + lv * 4) = v4;
    }

    int tx = threadIdx.x & 15;      // l micro
    int ty = threadIdx.x >> 4;      // o micro

    for (int ot = 0; ot < 8; ot++) {
        int obase = ot * 64;
        const float* wsrc = (obase < 256) ? (qk_w + (size_t)obase * C_)
                                          : (v_w + (size_t)(obase - 256) * C_);
        __syncthreads();
        for (int idx = threadIdx.x; idx < 64 * 32; idx += 256) {
            int o = idx >> 5, kv = idx & 31;
            float4 v4 = *(const float4*)(wsrc + (size_t)o * C_ + kv * 4);
            ws[(kv * 4 + 0) * 65 + o] = v4.x;
            ws[(kv * 4 + 1) * 65 + o] = v4.y;
            ws[(kv * 4 + 2) * 65 + o] = v4.z;
            ws[(kv * 4 + 3) * 65 + o] = v4.w;
        }
        __syncthreads();

        float acc[4][4] = {};
        #pragma unroll 4
        for (int kk = 0; kk < 128; kk++) {
            float a0 = ws[kk * 65 + ty * 4 + 0];
            float a1 = ws[kk * 65 + ty * 4 + 1];
            float a2 = ws[kk * 65 + ty * 4 + 2];
            float a3 = ws[kk * 65 + ty * 4 + 3];
            float4 b = *(const float4*)(xs + kk * 64 + tx * 4);
            acc[0][0] += a0 * b.x; acc[0][1] += a0 * b.y; acc[0][2] += a0 * b.z; acc[0][3] += a0 * b.w;
            acc[1][0] += a1 * b.x; acc[1][1] += a1 * b.y; acc[1][2] += a1 * b.z; acc[1][3] += a1 * b.w;
            acc[2][0] += a2 * b.x; acc[2][1] += a2 * b.y; acc[2][2] += a2 * b.z; acc[2][3] += a2 * b.w;
            acc[3][0] += a3 * b.x; acc[3][1] += a3 * b.y; acc[3][2] += a3 * b.z; acc[3][3] += a3 * b.w;
        }

        #pragma unroll
        for (int i = 0; i < 4; i++) {
            int oo = obase + ty * 4 + i;
            float* dst;
            if (oo < 128) {
                int head = oo >> 6, d = oo & 63;
                dst = g_q + ((size_t)(bs * 2 + head) * QKD_ + d) * L_;
            } else if (oo < 256) {
                int o2 = oo - 128;
                int head = o2 >> 6, d = o2 & 63;
                dst = g_k + ((size_t)(bs * 2 + head) * QKD_ + d) * L_;
            } else {
                int o2 = oo - 256;
                int head = o2 >> 7, d = o2 & 127;
                dst = g_v + ((size_t)(bs * 2 + head) * VD_ + d) * L_;
            }
            float4 r = make_float4(acc[i][0], acc[i][1], acc[i][2], acc[i][3]);
            *(float4*)(dst + l0 + tx * 4) = r;
        }
    }
}

// ---------------- kernel 3: fused attention ----------------
// Block: (q-tile of 32 rows, bs*head). 256 threads.
// smem: qs[64][32], ks[64][64], vs[128][65], sc[32][600]
#define SCW 600
__global__ void attn_kernel(const float* __restrict__ sa_bias) {
    int qt = blockIdx.x;              // 0..17
    int bh = blockIdx.y;              // 0..127
    int bs = bh >> 1, head = bh & 1;
    int q0 = qt * 32;

    extern __shared__ float sm[];
    float* qs = sm;                          // 2048
    float* ks = qs + 64 * 32;                // 4096
    float* vs = ks + 64 * 64;                // 8320
    float* sc = vs + 128 * 65;               // 19200

    const float* qg = g_q + (size_t)(bs * 2 + head) * QKD_ * L_;
    const float* kg = g_k + (size_t)(bs * 2 + head) * QKD_ * L_;
    const float* vg = g_v + (size_t)(bs * 2 + head) * VD_ * L_;
    const float* bg = g_bias + (size_t)head * L_ * L_;

    int tid = threadIdx.x;

    // load q tile (d-major)
    for (int idx = tid; idx < 64 * 8; idx += 256) {
        int d = idx >> 3, jv = idx & 7;
        *(float4*)(qs + d * 32 + jv * 4) =
            *(const float4*)(qg + (size_t)d * L_ + q0 + jv * 4);
    }

    int r = tid >> 3;        // query row 0..31
    int cg = tid & 7;        // column group

    // ---- scores ----
    for (int kt = 0; kt < 9; kt++) {
        int k0 = kt * 64;
        __syncthreads();
        for (int idx = tid; idx < 64 * 16; idx += 256) {
            int d = idx >> 4, mv = idx & 15;
            *(float4*)(ks + d * 64 + mv * 4) =
                *(const float4*)(kg + (size_t)d * L_ + k0 + mv * 4);
        }
        __syncthreads();

        float acc[8] = {};
        #pragma unroll 4
        for (int kk = 0; kk < 64; kk++) {
            float a = qs[kk * 32 + r];
            #pragma unroll
            for (int jj = 0; jj < 8; jj++)
                acc[jj] += a * ks[kk * 64 + cg + 8 * jj];
        }
        const float* brow = bg + (size_t)(q0 + r) * L_ + k0;
        #pragma unroll
        for (int jj = 0; jj < 8; jj++) {
            int key = cg + 8 * jj;
            sc[r * SCW + k0 + key] = acc[jj] * 0.125f + brow[key];
        }
    }
    __syncthreads();

    // ---- softmax (8 lanes per row, warp-local) ----
    {
        float mx = -1e30f;
        for (int i = cg; i < L_; i += 8) mx = fmaxf(mx, sc[r * SCW + i]);
        #pragma unroll
        for (int off = 1; off < 8; off <<= 1)
            mx = fmaxf(mx, __shfl_xor_sync(0xffffffffu, mx, off));
        float sum = 0.f;
        for (int i = cg; i < L_; i += 8) {
            float e = __expf(sc[r * SCW + i] - mx);
            sc[r * SCW + i] = e;
            sum += e;
        }
        #pragma unroll
        for (int off = 1; off < 8; off <<= 1)
            sum += __shfl_xor_sync(0xffffffffu, sum, off);
        float inv = 1.0f / sum;
        for (int i = cg; i < L_; i += 8) sc[r * SCW + i] *= inv;
    }
    __syncthreads();

    // ---- AV ----
    int rt = tid >> 5;       // warp id = row-quad
    int dt = tid & 31;       // d = dt + 32*i
    float oacc[4][4] = {};
    for (int vt = 0; vt < 9; vt++) {
        int m0 = vt * 64;
        __syncthreads();
        for (int idx = tid; idx < 128 * 16; idx += 256) {
            int d = idx >> 4, mv = idx & 15;
            float4 v4 = *(const float4*)(vg + (size_t)d * L_ + m0 + mv * 4);
            vs[d * 65 + mv * 4 + 0] = v4.x;
            vs[d * 65 + mv * 4 + 1] = v4.y;
            vs[d * 65 + mv * 4 + 2] = v4.z;
            vs[d * 65 + mv * 4 + 3] = v4.w;
        }
        __syncthreads();
        #pragma unroll 2
        for (int m = 0; m < 64; m++) {
            float p0 = sc[(rt * 4 + 0) * SCW + m0 + m];
            float p1 = sc[(rt * 4 + 1) * SCW + m0 + m];
            float p2 = sc[(rt * 4 + 2) * SCW + m0 + m];
            float p3 = sc[(rt * 4 + 3) * SCW + m0 + m];
            #pragma unroll
            for (int i = 0; i < 4; i++) {
                float vv = vs[(dt + 32 * i) * 65 + m];
                oacc[0][i] += p0 * vv;
                oacc[1][i] += p1 * vv;
                oacc[2][i] += p2 * vv;
                oacc[3][i] += p3 * vv;
            }
        }
    }

    float* og = g_att + (size_t)bs * L_ * HID_;
    #pragma unroll
    for (int rr = 0; rr < 4; rr++) {
        int l = q0 + rt * 4 + rr;
        #pragma unroll
        for (int i = 0; i < 4; i++) {
            int ch = head * 128 + dt + 32 * i;
            og[(size_t)l * HID_ + ch] = oacc[rr][i] + sa_bias[ch];
        }
    }
}

// ---------------- kernel 4: 1x1-conv MLP with exact GELU ----------------
// Block handles 16 consecutive positions of one bs. 256 threads.
// smem: ins[16][256] (reused as outs[16][132]), wt[256][65], y1s[16][260]
__global__ void mlp_kernel(const float* __restrict__ w1, const float* __restrict__ b1,
                           const float* __restrict__ w2, const float* __restrict__ b2,
                           float* __restrict__ out) {
    int blk = blockIdx.x;                  // 0..2303
    int bs = blk / 36;
    int l0 = (blk % 36) * 16;
    extern __shared__ float sm[];
    float* ins = sm;                       // 4096 floats
    float* wt  = sm + 16 * 256;            // 16640 floats  [256][65]
    float* y1s = wt + 256 * 65;            // 4160 floats   [16][260]

    int tid = threadIdx.x;
    const float* ag = g_att + ((size_t)bs * L_ + l0) * HID_;
    for (int idx = tid; idx < 16 * 64; idx += 256) {
        int p = idx >> 6, iv = idx & 63;
        *(float4*)(ins + p * 256 + iv * 4) = *(const float4*)(ag + p * 256 + iv * 4);
    }

    // phase 1: y1 = gelu(w1 @ in + b1), thread = output channel (256)
    float acc[16] = {};
    for (int it = 0; it < 4; it++) {
        __syncthreads();
        for (int idx = tid; idx < 256 * 16; idx += 256) {
            int o = idx >> 4, iv = idx & 15;
            float4 v4 = *(const float4*)(w1 + (size_t)o * 256 + it * 64 + iv * 4);
            wt[o * 65 + iv * 4 + 0] = v4.x;
            wt[o * 65 + iv * 4 + 1] = v4.y;
            wt[o * 65 + iv * 4 + 2] = v4.z;
            wt[o * 65 + iv * 4 + 3] = v4.w;
        }
        __syncthreads();
        int ib = it * 64;
        #pragma unroll 2
        for (int i = 0; i < 64; i++) {
            float wv = wt[tid * 65 + i];
            #pragma unroll
            for (int p = 0; p < 16; p++)
                acc[p] += wv * ins[p * 256 + ib + i];
        }
    }
    {
        float bb = b1[tid];
        #pragma unroll
        for (int p = 0; p < 16; p++) {
            float xv = acc[p] + bb;
            y1s[p * 260 + tid] = 0.5f * xv * (1.0f + erff(xv * 0.70710678118654752f));
        }
    }

    // phase 2: y2 = w2 @ y1 + b2, thread = (o2 = tid&127, position-half = tid>>7)
    int o2 = tid & 127, ph = tid >> 7;
    float acc2[8] = {};
    for (int it = 0; it < 4; it++) {
        __syncthreads();
        for (int idx = tid; idx < 128 * 16; idx += 256) {
            int o = idx >> 4, iv = idx & 15;
            float4 v4 = *(const float4*)(w2 + (size_t)o * 256 + it * 64 + iv * 4);
            wt[o * 65 + iv * 4 + 0] = v4.x;
            wt[o * 65 + iv * 4 + 1] = v4.y;
            wt[o * 65 + iv * 4 + 2] = v4.z;
            wt[o * 65 + iv * 4 + 3] = v4.w;
        }
        __syncthreads();
        int ib = it * 64;
        #pragma unroll 2
        for (int i = 0; i < 64; i++) {
            float wv = wt[o2 * 65 + i];
            #pragma unroll
            for (int p = 0; p < 8; p++)
                acc2[p] += wv * y1s[(ph * 8 + p) * 260 + ib + i];
        }
    }
    float b2v = b2[o2];
    __syncthreads();                       // last ins readers long done; reuse as outs
    #pragma unroll
    for (int p = 0; p < 8; p++)
        ins[(ph * 8 + p) * 132 + o2] = acc2[p] + b2v;
    __syncthreads();

    float* og = out + (size_t)bs * OUTC_ * L_;
    for (int idx = tid; idx < 128 * 16; idx += 256) {
        int o = idx >> 4, p = idx & 15;
        og[(size_t)o * L_ + l0 + p] = ins[p * 132 + o];
    }
}

// ---------------- launch ----------------
extern "C" void kernel_launch(void* const* d_in, const int* in_sizes, int n_in,
                              void* d_out, int out_size) {
    const float* x      = (const float*)d_in[0];
    const float* qk_w   = (const float*)d_in[1];
    const float* v_w    = (const float*)d_in[2];
    const float* cpb_w1 = (const float*)d_in[3];
    const float* cpb_b1 = (const float*)d_in[4];
    const float* cpb_w2 = (const float*)d_in[5];
    const float* sa_b   = (const float*)d_in[6];
    const float* mlp_w1 = (const float*)d_in[7];
    const float* mlp_b1 = (const float*)d_in[8];
    const float* mlp_w2 = (const float*)d_in[9];
    const float* mlp_b2 = (const float*)d_in[10];
    float* out = (float*)d_out;

    const int SMEM_QKV = (128 * 64 + 128 * 65) * 4;                         // 66048
    const int SMEM_ATT = (64 * 32 + 64 * 64 + 128 * 65 + 32 * SCW) * 4;    // 134656
    const int SMEM_MLP = (16 * 256 + 256 * 65 + 16 * 260) * 4;             // 99584

    cudaFuncSetAttribute(qkv_kernel,  cudaFuncAttributeMaxDynamicSharedMemorySize, SMEM_QKV);
    cudaFuncSetAttribute(attn_kernel, cudaFuncAttributeMaxDynamicSharedMemorySize, SMEM_ATT);
    cudaFuncSetAttribute(mlp_kernel,  cudaFuncAttributeMaxDynamicSharedMemorySize, SMEM_MLP);

    cpb_bias_kernel<<<(L_ * L_) / 256, 256>>>(cpb_w1, cpb_b1, cpb_w2);
    qkv_kernel<<<dim3(9, BS_), 256, SMEM_QKV>>>(x, qk_w, v_w);
    attn_kernel<<<dim3(18, BS_ * HEADS_), 256, SMEM_ATT>>>(sa_b);
    mlp_kernel<<<BS_ * 36, 256, SMEM_MLP>>>(mlp_w1, mlp_b1, mlp_w2, mlp_b2, out);
}

// round 3
// speedup vs baseline: 2.5988x; 2.5988x over previous
#include <cuda_runtime.h>
#include <cuda_bf16.h>
#include <math.h>

#define B_     2
#define S_     32
#define BS_    64
#define C_     128
#define HGT    24
#define WID    24
#define L_     576
#define HEADS_ 2
#define QKD_   64
#define VD_    128
#define HID_   256
#define OUTC_  128

// ---------------- scratch (static device globals; no allocation) ----------------
__device__ float g_bias[HEADS_ * L_ * L_];            // (head, i, j)
__device__ float g_q[BS_ * HEADS_ * L_ * QKD_];       // (bs,head,l,d)  l-major
__device__ float g_k[BS_ * HEADS_ * L_ * QKD_];
__device__ float g_v[BS_ * HEADS_ * L_ * VD_];
__device__ float g_att[BS_ * L_ * HID_];              // (bs,l,ch) position-major

// ---------------- tf32 mma helpers ----------------
__device__ __forceinline__ unsigned f2tf(float f) {
    unsigned r;
    asm("cvt.rna.tf32.f32 %0, %1;" : "=r"(r) : "f"(f));
    return r;
}
__device__ __forceinline__ void mma_tf32(float c[4],
                                         unsigned a0, unsigned a1, unsigned a2, unsigned a3,
                                         unsigned b0, unsigned b1) {
    asm volatile(
        "mma.sync.aligned.m16n8k8.row.col.f32.tf32.tf32.f32 "
        "{%0,%1,%2,%3}, {%4,%5,%6,%7}, {%8,%9}, {%0,%1,%2,%3};"
        : "+f"(c[0]), "+f"(c[1]), "+f"(c[2]), "+f"(c[3])
        : "r"(a0), "r"(a1), "r"(a2), "r"(a3), "r"(b0), "r"(b1));
}

// ---------------- kernel 1: continuous relative position bias ----------------
__global__ void cpb_bias_kernel(const float* __restrict__ w1,
                                const float* __restrict__ b1,
                                const float* __restrict__ w2) {
    __shared__ float s_w1[256];
    __shared__ float s_b1[128];
    __shared__ float s_w2[256];
    int tid = threadIdx.x;
    s_w1[tid] = w1[tid];
    if (tid < 128) s_b1[tid] = b1[tid];
    s_w2[tid] = w2[tid];
    __syncthreads();

    int idx = blockIdx.x * 256 + tid;      // < 576*576
    int i = idx / L_, j = idx % L_;
    int yi = i / WID, xi = i % WID;
    int yj = j / WID, xj = j % WID;
    float ry = (float)(yi - yj) * (8.0f / 23.0f);
    float rx = (float)(xi - xj) * (8.0f / 23.0f);
    ry = copysignf(log2f(1.0f + fabsf(ry)) * (1.0f / 3.0f), ry);
    rx = copysignf(log2f(1.0f + fabsf(rx)) * (1.0f / 3.0f), rx);

    float acc0 = 0.f, acc1 = 0.f;
    #pragma unroll 4
    for (int k = 0; k < 128; k++) {
        float h = fmaxf(0.f, ry * s_w1[2 * k] + rx * s_w1[2 * k + 1] + s_b1[k]);
        acc0 += h * s_w2[k];
        acc1 += h * s_w2[128 + k];
    }
    g_bias[idx] = acc0;
    g_bias[L_ * L_ + idx] = acc1;
}

// ---------------- kernel 2: QKV projection, tf32 mma ----------------
// Block: (l-tile 64, bs). 256 threads = 8 warps.
// smem: xs[128][72] (c-major), ws[64][132] (o-chunk of W), outs[64][68] transpose buf.
__global__ void qkv_kernel(const float* __restrict__ x,
                           const float* __restrict__ qk_w,
                           const float* __restrict__ v_w) {
    int bs = blockIdx.y;
    int l0 = blockIdx.x * 64;
    extern __shared__ float sm[];
    float* xs   = sm;                  // 128*72
    float* ws   = xs + 128 * 72;       // 64*132
    float* outs = ws + 64 * 132;       // 64*68

    int tid = threadIdx.x;
    const float* xb = x + (size_t)bs * C_ * L_;
    for (int idx = tid; idx < 128 * 16; idx += 256) {
        int c = idx >> 4, lv = idx & 15;
        *(float4*)(xs + c * 72 + lv * 4) = *(const float4*)(xb + (size_t)c * L_ + l0 + lv * 4);
    }

    int warp = tid >> 5, lane = tid & 31;
    int row = lane >> 2, quad = lane & 3;
    int m0 = (warp & 3) * 16;           // o within chunk
    int n0 = (warp >> 2) * 32;          // l within tile

    for (int ot = 0; ot < 8; ot++) {
        const float* wsrc = (ot < 4) ? qk_w + (size_t)ot * 64 * C_
                                     : v_w  + (size_t)(ot - 4) * 64 * C_;
        __syncthreads();
        for (int idx = tid; idx < 64 * 32; idx += 256) {
            int o = idx >> 5, kv = idx & 31;
            *(float4*)(ws + o * 132 + kv * 4) = *(const float4*)(wsrc + (size_t)o * C_ + kv * 4);
        }
        __syncthreads();

        float acc[4][4] = {};
        #pragma unroll
        for (int kk = 0; kk < 16; kk++) {
            int k0 = kk * 8;
            unsigned a0 = f2tf(ws[(m0 + row) * 132 + k0 + quad]);
            unsigned a1 = f2tf(ws[(m0 + row + 8) * 132 + k0 + quad]);
            unsigned a2 = f2tf(ws[(m0 + row) * 132 + k0 + quad + 4]);
            unsigned a3 = f2tf(ws[(m0 + row + 8) * 132 + k0 + quad + 4]);
            #pragma unroll
            for (int nt = 0; nt < 4; nt++) {
                int n = n0 + nt * 8;
                unsigned b0 = f2tf(xs[(k0 + quad) * 72 + n + row]);
                unsigned b1 = f2tf(xs[(k0 + quad + 4) * 72 + n + row]);
                mma_tf32(acc[nt], a0, a1, a2, a3, b0, b1);
            }
        }

        // transpose into outs[l][o]
        #pragma unroll
        for (int nt = 0; nt < 4; nt++) {
            int n = n0 + nt * 8 + 2 * quad;
            outs[n * 68 + m0 + row]           = acc[nt][0];
            outs[(n + 1) * 68 + m0 + row]     = acc[nt][1];
            outs[n * 68 + m0 + row + 8]       = acc[nt][2];
            outs[(n + 1) * 68 + m0 + row + 8] = acc[nt][3];
        }
        __syncthreads();

        float* dst; int stride, dof;
        if (ot < 2)      { dst = g_q + (size_t)(bs * 2 + ot) * L_ * QKD_;     stride = QKD_; dof = 0; }
        else if (ot < 4) { dst = g_k + (size_t)(bs * 2 + ot - 2) * L_ * QKD_; stride = QKD_; dof = 0; }
        else {
            int o2 = (ot - 4) * 64;
            int head = o2 >> 7; dof = o2 & 127;
            dst = g_v + (size_t)(bs * 2 + head) * L_ * VD_; stride = VD_;
        }
        for (int idx = tid; idx < 64 * 16; idx += 256) {
            int l = idx >> 4, j = idx & 15;
            *(float4*)(dst + (size_t)(l0 + l) * stride + dof + j * 4) =
                *(float4*)(outs + l * 68 + j * 4);
        }
    }
}

// ---------------- kernel 3: fused attention, tf32 mma ----------------
// Block: (q-tile 64, bs*head). 256 threads = 8 warps.
// smem: qs[64][68], ks[64][68], vs[64][136], sc[64][580]
__global__ void attn_kernel(const float* __restrict__ sa_bias) {
    int qt = blockIdx.x;              // 0..8
    int bh = blockIdx.y;              // 0..127
    int bs = bh >> 1, head = bh & 1;
    int q0 = qt * 64;

    extern __shared__ float sm[];
    float* qs = sm;                    // 64*68
    float* ks = qs + 64 * 68;          // 64*68
    float* vs = ks + 64 * 68;          // 64*136
    float* sc = vs + 64 * 136;         // 64*580

    const float* qg = g_q + (size_t)(bs * 2 + head) * L_ * QKD_;
    const float* kg = g_k + (size_t)(bs * 2 + head) * L_ * QKD_;
    const float* vg = g_v + (size_t)(bs * 2 + head) * L_ * VD_;
    const float* bg = g_bias + (size_t)head * L_ * L_;

    int tid = threadIdx.x;
    int warp = tid >> 5, lane = tid & 31;
    int row = lane >> 2, quad = lane & 3;
    int m0 = (warp & 3) * 16;          // q rows

    // load q tile [64][64]
    for (int idx = tid; idx < 64 * 16; idx += 256) {
        int l = idx >> 4, dv = idx & 15;
        *(float4*)(qs + l * 68 + dv * 4) = *(const float4*)(qg + (size_t)(q0 + l) * QKD_ + dv * 4);
    }

    // ---- scores ----
    {
        int n0 = (warp >> 2) * 32;     // key cols within 64-tile
        for (int kt = 0; kt < 9; kt++) {
            __syncthreads();
            for (int idx = tid; idx < 64 * 16; idx += 256) {
                int l = idx >> 4, dv = idx & 15;
                *(float4*)(ks + l * 68 + dv * 4) =
                    *(const float4*)(kg + (size_t)(kt * 64 + l) * QKD_ + dv * 4);
            }
            __syncthreads();

            float acc[4][4] = {};
            #pragma unroll
            for (int kk = 0; kk < 8; kk++) {
                int k0 = kk * 8;
                unsigned a0 = f2tf(qs[(m0 + row) * 68 + k0 + quad]);
                unsigned a1 = f2tf(qs[(m0 + row + 8) * 68 + k0 + quad]);
                unsigned a2 = f2tf(qs[(m0 + row) * 68 + k0 + quad + 4]);
                unsigned a3 = f2tf(qs[(m0 + row + 8) * 68 + k0 + quad + 4]);
                #pragma unroll
                for (int nt = 0; nt < 4; nt++) {
                    int n = n0 + nt * 8;
                    unsigned b0 = f2tf(ks[(n + row) * 68 + k0 + quad]);
                    unsigned b1 = f2tf(ks[(n + row) * 68 + k0 + quad + 4]);
                    mma_tf32(acc[nt], a0, a1, a2, a3, b0, b1);
                }
            }

            int r0 = q0 + m0 + row;
            #pragma unroll
            for (int nt = 0; nt < 4; nt++) {
                int colg = kt * 64 + n0 + nt * 8 + 2 * quad;
                sc[(m0 + row) * 580 + colg]         = acc[nt][0] * 0.125f + bg[(size_t)r0 * L_ + colg];
                sc[(m0 + row) * 580 + colg + 1]     = acc[nt][1] * 0.125f + bg[(size_t)r0 * L_ + colg + 1];
                sc[(m0 + row + 8) * 580 + colg]     = acc[nt][2] * 0.125f + bg[(size_t)(r0 + 8) * L_ + colg];
                sc[(m0 + row + 8) * 580 + colg + 1] = acc[nt][3] * 0.125f + bg[(size_t)(r0 + 8) * L_ + colg + 1];
            }
        }
    }
    __syncthreads();

    // ---- softmax: each warp handles 8 rows ----
    for (int rr = 0; rr < 8; rr++) {
        int r = warp * 8 + rr;
        float mx = -1e30f;
        for (int i = lane; i < L_; i += 32) mx = fmaxf(mx, sc[r * 580 + i]);
        #pragma unroll
        for (int off = 16; off > 0; off >>= 1)
            mx = fmaxf(mx, __shfl_xor_sync(0xffffffffu, mx, off));
        float sum = 0.f;
        for (int i = lane; i < L_; i += 32) {
            float e = __expf(sc[r * 580 + i] - mx);
            sc[r * 580 + i] = e;
            sum += e;
        }
        #pragma unroll
        for (int off = 16; off > 0; off >>= 1)
            sum += __shfl_xor_sync(0xffffffffu, sum, off);
        float inv = 1.0f / sum;
        for (int i = lane; i < L_; i += 32) sc[r * 580 + i] *= inv;
    }
    __syncthreads();

    // ---- AV: output 64 x 128, warps cover m in 4x16, n in 2x64 ----
    {
        int n0 = (warp >> 2) * 64;     // d-cols: 0 or 64
        float oac[8][4] = {};
        for (int vt = 0; vt < 9; vt++) {
            for (int idx = tid; idx < 64 * 32; idx += 256) {
                int l = idx >> 5, dv = idx & 31;
                *(float4*)(vs + l * 136 + dv * 4) =
                    *(const float4*)(vg + (size_t)(vt * 64 + l) * VD_ + dv * 4);
            }
            __syncthreads();
            #pragma unroll
            for (int kk = 0; kk < 8; kk++) {
                int k0 = kk * 8;
                unsigned a0 = f2tf(sc[(m0 + row) * 580 + vt * 64 + k0 + quad]);
                unsigned a1 = f2tf(sc[(m0 + row + 8) * 580 + vt * 64 + k0 + quad]);
                unsigned a2 = f2tf(sc[(m0 + row) * 580 + vt * 64 + k0 + quad + 4]);
                unsigned a3 = f2tf(sc[(m0 + row + 8) * 580 + vt * 64 + k0 + quad + 4]);
                #pragma unroll
                for (int nt = 0; nt < 8; nt++) {
                    int n = n0 + nt * 8;
                    unsigned b0 = f2tf(vs[(k0 + quad) * 136 + n + row]);
                    unsigned b1 = f2tf(vs[(k0 + quad + 4) * 136 + n + row]);
                    mma_tf32(oac[nt], a0, a1, a2, a3, b0, b1);
                }
            }
            __syncthreads();
        }

        // ---- write out + sa_bias ----
        float* og = g_att + (size_t)bs * L_ * HID_;
        int l = q0 + m0 + row;
        #pragma unroll
        for (int nt = 0; nt < 8; nt++) {
            int ch = head * 128 + n0 + nt * 8 + 2 * quad;
            float sb0 = sa_bias[ch], sb1 = sa_bias[ch + 1];
            og[(size_t)l * HID_ + ch]           = oac[nt][0] + sb0;
            og[(size_t)l * HID_ + ch + 1]       = oac[nt][1] + sb1;
            og[(size_t)(l + 8) * HID_ + ch]     = oac[nt][2] + sb0;
            og[(size_t)(l + 8) * HID_ + ch + 1] = oac[nt][3] + sb1;
        }
    }
}

// ---------------- kernel 4: MLP (tf32 mma) with exact GELU ----------------
// Block: 64 positions of one bs. 256 threads = 8 warps.
// smem: xsm[64][260], wts[256][68], y1s[64][260]
__global__ void mlp_kernel(const float* __restrict__ w1, const float* __restrict__ b1,
                           const float* __restrict__ w2, const float* __restrict__ b2,
                           float* __restrict__ out) {
    int blk = blockIdx.x;                // 0..575
    int bs = blk / 9;
    int l0 = (blk % 9) * 64;
    extern __shared__ float sm[];
    float* xsm = sm;                     // 64*260
    float* wts = xsm + 64 * 260;         // 256*68
    float* y1s = wts + 256 * 68;         // 64*260

    int tid = threadIdx.x;
    int warp = tid >> 5, lane = tid & 31;
    int row = lane >> 2, quad = lane & 3;

    const float* ag = g_att + ((size_t)bs * L_ + l0) * HID_;
    for (int idx = tid; idx < 64 * 64; idx += 256) {
        int p = idx >> 6, iv = idx & 63;
        *(float4*)(xsm + p * 260 + iv * 4) = *(const float4*)(ag + (size_t)p * HID_ + iv * 4);
    }

    // ---- GEMM1: Y1(64x256) = X(64x256) @ W1^T ----
    int m0 = (warp & 1) * 32;            // positions
    int n0 = (warp >> 1) * 64;           // hid outputs
    float acc[2][8][4] = {};
    for (int it = 0; it < 4; it++) {
        __syncthreads();
        for (int idx = tid; idx < 256 * 16; idx += 256) {
            int o = idx >> 4, kv = idx & 15;
            *(float4*)(wts + o * 68 + kv * 4) = *(const float4*)(w1 + (size_t)o * HID_ + it * 64 + kv * 4);
        }
        __syncthreads();
        #pragma unroll
        for (int kk = 0; kk < 8; kk++) {
            int kg = it * 64 + kk * 8;
            int ks0 = kk * 8;
            unsigned a[2][4];
            #pragma unroll
            for (int mt = 0; mt < 2; mt++) {
                a[mt][0] = f2tf(xsm[(m0 + mt * 16 + row) * 260 + kg + quad]);
                a[mt][1] = f2tf(xsm[(m0 + mt * 16 + row + 8) * 260 + kg + quad]);
                a[mt][2] = f2tf(xsm[(m0 + mt * 16 + row) * 260 + kg + quad + 4]);
                a[mt][3] = f2tf(xsm[(m0 + mt * 16 + row + 8) * 260 + kg + quad + 4]);
            }
            #pragma unroll
            for (int nt = 0; nt < 8; nt++) {
                unsigned b0 = f2tf(wts[(n0 + nt * 8 + row) * 68 + ks0 + quad]);
                unsigned b1 = f2tf(wts[(n0 + nt * 8 + row) * 68 + ks0 + quad + 4]);
                mma_tf32(acc[0][nt], a[0][0], a[0][1], a[0][2], a[0][3], b0, b1);
                mma_tf32(acc[1][nt], a[1][0], a[1][1], a[1][2], a[1][3], b0, b1);
            }
        }
    }
    // bias + exact GELU -> y1s[p][o]
    #pragma unroll
    for (int mt = 0; mt < 2; mt++) {
        #pragma unroll
        for (int nt = 0; nt < 8; nt++) {
            int col = n0 + nt * 8 + 2 * quad;
            float bb0 = b1[col], bb1 = b1[col + 1];
            int r = m0 + mt * 16 + row;
            float v0 = acc[mt][nt][0] + bb0;
            float v1 = acc[mt][nt][1] + bb1;
            float v2 = acc[mt][nt][2] + bb0;
            float v3 = acc[mt][nt][3] + bb1;
            y1s[r * 260 + col]           = 0.5f * v0 * (1.0f + erff(v0 * 0.70710678118654752f));
            y1s[r * 260 + col + 1]       = 0.5f * v1 * (1.0f + erff(v1 * 0.70710678118654752f));
            y1s[(r + 8) * 260 + col]     = 0.5f * v2 * (1.0f + erff(v2 * 0.70710678118654752f));
            y1s[(r + 8) * 260 + col + 1] = 0.5f * v3 * (1.0f + erff(v3 * 0.70710678118654752f));
        }
    }
    __syncthreads();

    // ---- GEMM2: OUT(64x128) = Y1(64x256) @ W2^T ----
    int n0b = (warp >> 1) * 32;
    float ac2[2][4][4] = {};
    for (int it = 0; it < 4; it++) {
        for (int idx = tid; idx < 128 * 16; idx += 256) {
            int o = idx >> 4, kv = idx & 15;
            *(float4*)(wts + o * 68 + kv * 4) = *(const float4*)(w2 + (size_t)o * HID_ + it * 64 + kv * 4);
        }
        __syncthreads();
        #pragma unroll
        for (int kk = 0; kk < 8; kk++) {
            int kg = it * 64 + kk * 8;
            int ks0 = kk * 8;
            unsigned a[2][4];
            #pragma unroll
            for (int mt = 0; mt < 2; mt++) {
                a[mt][0] = f2tf(y1s[(m0 + mt * 16 + row) * 260 + kg + quad]);
                a[mt][1] = f2tf(y1s[(m0 + mt * 16 + row + 8) * 260 + kg + quad]);
                a[mt][2] = f2tf(y1s[(m0 + mt * 16 + row) * 260 + kg + quad + 4]);
                a[mt][3] = f2tf(y1s[(m0 + mt * 16 + row + 8) * 260 + kg + quad + 4]);
            }
            #pragma unroll
            for (int nt = 0; nt < 4; nt++) {
                unsigned b0 = f2tf(wts[(n0b + nt * 8 + row) * 68 + ks0 + quad]);
                unsigned b1 = f2tf(wts[(n0b + nt * 8 + row) * 68 + ks0 + quad + 4]);
                mma_tf32(ac2[0][nt], a[0][0], a[0][1], a[0][2], a[0][3], b0, b1);
                mma_tf32(ac2[1][nt], a[1][0], a[1][1], a[1][2], a[1][3], b0, b1);
            }
        }
        __syncthreads();
    }

    // ---- epilogue: + b2, write (bs, o, l) ----
    float* og = out + (size_t)bs * OUTC_ * L_;
    #pragma unroll
    for (int mt = 0; mt < 2; mt++) {
        int l = l0 + m0 + mt * 16 + row;
        #pragma unroll
        for (int nt = 0; nt < 4; nt++) {
            int col = n0b + nt * 8 + 2 * quad;
            float bb0 = b2[col], bb1 = b2[col + 1];
            og[(size_t)col * L_ + l]           = ac2[mt][nt][0] + bb0;
            og[(size_t)(col + 1) * L_ + l]     = ac2[mt][nt][1] + bb1;
            og[(size_t)col * L_ + l + 8]       = ac2[mt][nt][2] + bb0;
            og[(size_t)(col + 1) * L_ + l + 8] = ac2[mt][nt][3] + bb1;
        }
    }
}

// ---------------- launch ----------------
extern "C" void kernel_launch(void* const* d_in, const int* in_sizes, int n_in,
                              void* d_out, int out_size) {
    const float* x      = (const float*)d_in[0];
    const float* qk_w   = (const float*)d_in[1];
    const float* v_w    = (const float*)d_in[2];
    const float* cpb_w1 = (const float*)d_in[3];
    const float* cpb_b1 = (const float*)d_in[4];
    const float* cpb_w2 = (const float*)d_in[5];
    const float* sa_b   = (const float*)d_in[6];
    const float* mlp_w1 = (const float*)d_in[7];
    const float* mlp_b1 = (const float*)d_in[8];
    const float* mlp_w2 = (const float*)d_in[9];
    const float* mlp_b2 = (const float*)d_in[10];
    float* out = (float*)d_out;

    const int SMEM_QKV = (128 * 72 + 64 * 132 + 64 * 68) * 4;                 // 88064
    const int SMEM_ATT = (64 * 68 * 2 + 64 * 136 + 64 * 580) * 4;             // 218112
    const int SMEM_MLP = (64 * 260 + 256 * 68 + 64 * 260) * 4;                // 202752

    cudaFuncSetAttribute(qkv_kernel,  cudaFuncAttributeMaxDynamicSharedMemorySize, SMEM_QKV);
    cudaFuncSetAttribute(attn_kernel, cudaFuncAttributeMaxDynamicSharedMemorySize, SMEM_ATT);
    cudaFuncSetAttribute(mlp_kernel,  cudaFuncAttributeMaxDynamicSharedMemorySize, SMEM_MLP);

    cpb_bias_kernel<<<(L_ * L_) / 256, 256>>>(cpb_w1, cpb_b1, cpb_w2);
    qkv_kernel<<<dim3(9, BS_), 256, SMEM_QKV>>>(x, qk_w, v_w);
    attn_kernel<<<dim3(9, BS_ * HEADS_), 256, SMEM_ATT>>>(sa_b);
    mlp_kernel<<<BS_ * 9, 256, SMEM_MLP>>>(mlp_w1, mlp_b1, mlp_w2, mlp_b2, out);
}

// round 4
// speedup vs baseline: 3.1268x; 1.2032x over previous
#include <cuda_runtime.h>
#include <cuda_bf16.h>
#include <math.h>

#define B_     2
#define S_     32
#define BS_    64
#define C_     128
#define HGT    24
#define WID    24
#define L_     576
#define HEADS_ 2
#define QKD_   64
#define VD_    128
#define HID_   256
#define OUTC_  128

// ---------------- scratch (static device globals; no allocation) ----------------
__device__ float g_bias[HEADS_ * L_ * L_];            // (head, i, j)  fp32
__device__ float g_q[BS_ * HEADS_ * L_ * QKD_];       // tf32-rounded
__device__ float g_k[BS_ * HEADS_ * L_ * QKD_];       // tf32-rounded
__device__ float g_v[BS_ * HEADS_ * L_ * VD_];        // tf32-rounded
__device__ float g_att[BS_ * L_ * HID_];              // tf32-rounded

// ---------------- tf32 helpers ----------------
__device__ __forceinline__ unsigned f2tf(float f) {
    unsigned r;
    asm("cvt.rna.tf32.f32 %0, %1;" : "=r"(r) : "f"(f));
    return r;
}
__device__ __forceinline__ float tfr(float f) { return __uint_as_float(f2tf(f)); }
__device__ __forceinline__ void mma_tf32(float c[4],
                                         float a0, float a1, float a2, float a3,
                                         float b0, float b1) {
    asm volatile(
        "mma.sync.aligned.m16n8k8.row.col.f32.tf32.tf32.f32 "
        "{%0,%1,%2,%3}, {%4,%5,%6,%7}, {%8,%9}, {%0,%1,%2,%3};"
        : "+f"(c[0]), "+f"(c[1]), "+f"(c[2]), "+f"(c[3])
        : "r"(__float_as_uint(a0)), "r"(__float_as_uint(a1)),
          "r"(__float_as_uint(a2)), "r"(__float_as_uint(a3)),
          "r"(__float_as_uint(b0)), "r"(__float_as_uint(b1)));
}

// ---------------- kernel 1: continuous relative position bias ----------------
__global__ void cpb_bias_kernel(const float* __restrict__ w1,
                                const float* __restrict__ b1,
                                const float* __restrict__ w2) {
    __shared__ float s_w1[256];
    __shared__ float s_b1[128];
    __shared__ float s_w2[256];
    int tid = threadIdx.x;
    s_w1[tid] = w1[tid];
    if (tid < 128) s_b1[tid] = b1[tid];
    s_w2[tid] = w2[tid];
    __syncthreads();

    int idx = blockIdx.x * 256 + tid;      // < 576*576
    int i = idx / L_, j = idx % L_;
    int yi = i / WID, xi = i % WID;
    int yj = j / WID, xj = j % WID;
    float ry = (float)(yi - yj) * (8.0f / 23.0f);
    float rx = (float)(xi - xj) * (8.0f / 23.0f);
    ry = copysignf(log2f(1.0f + fabsf(ry)) * (1.0f / 3.0f), ry);
    rx = copysignf(log2f(1.0f + fabsf(rx)) * (1.0f / 3.0f), rx);

    float acc0 = 0.f, acc1 = 0.f;
    #pragma unroll 4
    for (int k = 0; k < 128; k++) {
        float h = fmaxf(0.f, ry * s_w1[2 * k] + rx * s_w1[2 * k + 1] + s_b1[k]);
        acc0 += h * s_w2[k];
        acc1 += h * s_w2[128 + k];
    }
    g_bias[idx] = acc0;
    g_bias[L_ * L_ + idx] = acc1;
}

// ---------------- kernel 2: QKV projection, tf32 mma ----------------
// Block: (l-tile 64, bs). 256 threads = 8 warps.
__global__ void qkv_kernel(const float* __restrict__ x,
                           const float* __restrict__ qk_w,
                           const float* __restrict__ v_w) {
    int bs = blockIdx.y;
    int l0 = blockIdx.x * 64;
    extern __shared__ float sm[];
    float* xs   = sm;                  // 128*72  (tf32-rounded)
    float* ws   = xs + 128 * 72;       // 64*132  (tf32-rounded)
    float* outs = ws + 64 * 132;       // 64*68

    int tid = threadIdx.x;
    const float* xb = x + (size_t)bs * C_ * L_;
    for (int idx = tid; idx < 128 * 16; idx += 256) {
        int c = idx >> 4, lv = idx & 15;
        float4 v4 = *(const float4*)(xb + (size_t)c * L_ + l0 + lv * 4);
        v4.x = tfr(v4.x); v4.y = tfr(v4.y); v4.z = tfr(v4.z); v4.w = tfr(v4.w);
        *(float4*)(xs + c * 72 + lv * 4) = v4;
    }

    int warp = tid >> 5, lane = tid & 31;
    int row = lane >> 2, quad = lane & 3;
    int m0 = (warp & 3) * 16;           // o within chunk
    int n0 = (warp >> 2) * 32;          // l within tile

    for (int ot = 0; ot < 8; ot++) {
        const float* wsrc = (ot < 4) ? qk_w + (size_t)ot * 64 * C_
                                     : v_w  + (size_t)(ot - 4) * 64 * C_;
        __syncthreads();
        for (int idx = tid; idx < 64 * 32; idx += 256) {
            int o = idx >> 5, kv = idx & 31;
            float4 v4 = *(const float4*)(wsrc + (size_t)o * C_ + kv * 4);
            v4.x = tfr(v4.x); v4.y = tfr(v4.y); v4.z = tfr(v4.z); v4.w = tfr(v4.w);
            *(float4*)(ws + o * 132 + kv * 4) = v4;
        }
        __syncthreads();

        float acc[4][4] = {};
        #pragma unroll
        for (int kk = 0; kk < 16; kk++) {
            int k0 = kk * 8;
            float a0 = ws[(m0 + row) * 132 + k0 + quad];
            float a1 = ws[(m0 + row + 8) * 132 + k0 + quad];
            float a2 = ws[(m0 + row) * 132 + k0 + quad + 4];
            float a3 = ws[(m0 + row + 8) * 132 + k0 + quad + 4];
            #pragma unroll
            for (int nt = 0; nt < 4; nt++) {
                int n = n0 + nt * 8;
                float b0 = xs[(k0 + quad) * 72 + n + row];
                float b1 = xs[(k0 + quad + 4) * 72 + n + row];
                mma_tf32(acc[nt], a0, a1, a2, a3, b0, b1);
            }
        }

        // transpose into outs[l][o], pre-rounded to tf32
        #pragma unroll
        for (int nt = 0; nt < 4; nt++) {
            int n = n0 + nt * 8 + 2 * quad;
            outs[n * 68 + m0 + row]           = tfr(acc[nt][0]);
            outs[(n + 1) * 68 + m0 + row]     = tfr(acc[nt][1]);
            outs[n * 68 + m0 + row + 8]       = tfr(acc[nt][2]);
            outs[(n + 1) * 68 + m0 + row + 8] = tfr(acc[nt][3]);
        }
        __syncthreads();

        float* dst; int stride, dof;
        if (ot < 2)      { dst = g_q + (size_t)(bs * 2 + ot) * L_ * QKD_;     stride = QKD_; dof = 0; }
        else if (ot < 4) { dst = g_k + (size_t)(bs * 2 + ot - 2) * L_ * QKD_; stride = QKD_; dof = 0; }
        else {
            int o2 = (ot - 4) * 64;
            int head = o2 >> 7; dof = o2 & 127;
            dst = g_v + (size_t)(bs * 2 + head) * L_ * VD_; stride = VD_;
        }
        for (int idx = tid; idx < 64 * 16; idx += 256) {
            int l = idx >> 4, j = idx & 15;
            *(float4*)(dst + (size_t)(l0 + l) * stride + dof + j * 4) =
                *(float4*)(outs + l * 68 + j * 4);
        }
    }
}

// ---------------- kernel 3: fused attention, tf32 mma, 512 threads = 16 warps ----------------
// smem: qs[64][68], ks[64][68], vs[64][136], sc[64][580]
__global__ void attn_kernel(const float* __restrict__ sa_bias) {
    int qt = blockIdx.x;              // 0..8
    int bh = blockIdx.y;              // 0..127
    int bs = bh >> 1, head = bh & 1;
    int q0 = qt * 64;

    extern __shared__ float sm[];
    float* qs = sm;                    // 64*68
    float* ks = qs + 64 * 68;          // 64*68
    float* vs = ks + 64 * 68;          // 64*136
    float* sc = vs + 64 * 136;         // 64*580

    const float* qg = g_q + (size_t)(bs * 2 + head) * L_ * QKD_;
    const float* kg = g_k + (size_t)(bs * 2 + head) * L_ * QKD_;
    const float* vg = g_v + (size_t)(bs * 2 + head) * L_ * VD_;
    const float* bg = g_bias + (size_t)head * L_ * L_;

    int tid = threadIdx.x;
    int warp = tid >> 5, lane = tid & 31;
    int row = lane >> 2, quad = lane & 3;
    int m0 = (warp & 3) * 16;          // q rows

    // load q tile [64][64] (already tf32-rounded)
    for (int idx = tid; idx < 64 * 16; idx += 512) {
        int l = idx >> 4, dv = idx & 15;
        *(float4*)(qs + l * 68 + dv * 4) = *(const float4*)(qg + (size_t)(q0 + l) * QKD_ + dv * 4);
    }

    // ---- scores: 16 warps cover 64x64 as m(4x16) x n(4x16) ----
    {
        int n0 = (warp >> 2) * 16;
        for (int kt = 0; kt < 9; kt++) {
            __syncthreads();
            for (int idx = tid; idx < 64 * 16; idx += 512) {
                int l = idx >> 4, dv = idx & 15;
                *(float4*)(ks + l * 68 + dv * 4) =
                    *(const float4*)(kg + (size_t)(kt * 64 + l) * QKD_ + dv * 4);
            }
            __syncthreads();

            float acc[2][4] = {};
            #pragma unroll
            for (int kk = 0; kk < 8; kk++) {
                int k0 = kk * 8;
                float a0 = qs[(m0 + row) * 68 + k0 + quad];
                float a1 = qs[(m0 + row + 8) * 68 + k0 + quad];
                float a2 = qs[(m0 + row) * 68 + k0 + quad + 4];
                float a3 = qs[(m0 + row + 8) * 68 + k0 + quad + 4];
                #pragma unroll
                for (int nt = 0; nt < 2; nt++) {
                    int n = n0 + nt * 8;
                    float b0 = ks[(n + row) * 68 + k0 + quad];
                    float b1 = ks[(n + row) * 68 + k0 + quad + 4];
                    mma_tf32(acc[nt], a0, a1, a2, a3, b0, b1);
                }
            }

            int r0 = q0 + m0 + row;
            #pragma unroll
            for (int nt = 0; nt < 2; nt++) {
                int colg = kt * 64 + n0 + nt * 8 + 2 * quad;
                sc[(m0 + row) * 580 + colg]         = acc[nt][0] * 0.125f + bg[(size_t)r0 * L_ + colg];
                sc[(m0 + row) * 580 + colg + 1]     = acc[nt][1] * 0.125f + bg[(size_t)r0 * L_ + colg + 1];
                sc[(m0 + row + 8) * 580 + colg]     = acc[nt][2] * 0.125f + bg[(size_t)(r0 + 8) * L_ + colg];
                sc[(m0 + row + 8) * 580 + colg + 1] = acc[nt][3] * 0.125f + bg[(size_t)(r0 + 8) * L_ + colg + 1];
            }
        }
    }
    __syncthreads();

    // ---- softmax: 16 warps x 4 rows, store tf32-rounded probabilities ----
    for (int rr = 0; rr < 4; rr++) {
        int r = warp * 4 + rr;
        float mx = -1e30f;
        for (int i = lane; i < L_; i += 32) mx = fmaxf(mx, sc[r * 580 + i]);
        #pragma unroll
        for (int off = 16; off > 0; off >>= 1)
            mx = fmaxf(mx, __shfl_xor_sync(0xffffffffu, mx, off));
        float sum = 0.f;
        for (int i = lane; i < L_; i += 32) {
            float e = __expf(sc[r * 580 + i] - mx);
            sc[r * 580 + i] = e;
            sum += e;
        }
        #pragma unroll
        for (int off = 16; off > 0; off >>= 1)
            sum += __shfl_xor_sync(0xffffffffu, sum, off);
        float inv = 1.0f / sum;
        for (int i = lane; i < L_; i += 32) sc[r * 580 + i] = tfr(sc[r * 580 + i] * inv);
    }
    __syncthreads();

    // ---- AV: 64x128 as m(4x16) x n(4x32) ----
    {
        int n0 = (warp >> 2) * 32;
        float oac[4][4] = {};
        for (int vt = 0; vt < 9; vt++) {
            for (int idx = tid; idx < 64 * 32; idx += 512) {
                int l = idx >> 5, dv = idx & 31;
                *(float4*)(vs + l * 136 + dv * 4) =
                    *(const float4*)(vg + (size_t)(vt * 64 + l) * VD_ + dv * 4);
            }
            __syncthreads();
            #pragma unroll
            for (int kk = 0; kk < 8; kk++) {
                int k0 = vt * 64 + kk * 8;
                float a0 = sc[(m0 + row) * 580 + k0 + quad];
                float a1 = sc[(m0 + row + 8) * 580 + k0 + quad];
                float a2 = sc[(m0 + row) * 580 + k0 + quad + 4];
                float a3 = sc[(m0 + row + 8) * 580 + k0 + quad + 4];
                #pragma unroll
                for (int nt = 0; nt < 4; nt++) {
                    int n = n0 + nt * 8;
                    float b0 = vs[(kk * 8 + quad) * 136 + n + row];
                    float b1 = vs[(kk * 8 + quad + 4) * 136 + n + row];
                    mma_tf32(oac[nt], a0, a1, a2, a3, b0, b1);
                }
            }
            __syncthreads();
        }

        // ---- write out + sa_bias, pre-rounded for the MLP ----
        float* og = g_att + (size_t)bs * L_ * HID_;
        int l = q0 + m0 + row;
        #pragma unroll
        for (int nt = 0; nt < 4; nt++) {
            int ch = head * 128 + n0 + nt * 8 + 2 * quad;
            float sb0 = sa_bias[ch], sb1 = sa_bias[ch + 1];
            og[(size_t)l * HID_ + ch]           = tfr(oac[nt][0] + sb0);
            og[(size_t)l * HID_ + ch + 1]       = tfr(oac[nt][1] + sb1);
            og[(size_t)(l + 8) * HID_ + ch]     = tfr(oac[nt][2] + sb0);
            og[(size_t)(l + 8) * HID_ + ch + 1] = tfr(oac[nt][3] + sb1);
        }
    }
}

// ---------------- kernel 4: MLP (tf32 mma), 512 threads = 16 warps ----------------
// smem: xsm[64][260], wts[256][68], y1s[64][260]
__global__ void mlp_kernel(const float* __restrict__ w1, const float* __restrict__ b1,
                           const float* __restrict__ w2, const float* __restrict__ b2,
                           float* __restrict__ out) {
    int blk = blockIdx.x;                // 0..575
    int bs = blk / 9;
    int l0 = (blk % 9) * 64;
    extern __shared__ float sm[];
    float* xsm = sm;                     // 64*260
    float* wts = xsm + 64 * 260;         // 256*68
    float* y1s = wts + 256 * 68;         // 64*260

    int tid = threadIdx.x;
    int warp = tid >> 5, lane = tid & 31;
    int row = lane >> 2, quad = lane & 3;

    const float* ag = g_att + ((size_t)bs * L_ + l0) * HID_;
    for (int idx = tid; idx < 64 * 64; idx += 512) {
        int p = idx >> 6, iv = idx & 63;
        *(float4*)(xsm + p * 260 + iv * 4) = *(const float4*)(ag + (size_t)p * HID_ + iv * 4);
    }

    // ---- GEMM1: Y1(64x256) = X @ W1^T : m(2x32) x n(8x32) ----
    int m0 = (warp & 1) * 32;
    int n0 = (warp >> 1) * 32;
    float acc[2][4][4] = {};
    for (int it = 0; it < 4; it++) {
        __syncthreads();
        for (int idx = tid; idx < 256 * 16; idx += 512) {
            int o = idx >> 4, kv = idx & 15;
            float4 v4 = *(const float4*)(w1 + (size_t)o * HID_ + it * 64 + kv * 4);
            v4.x = tfr(v4.x); v4.y = tfr(v4.y); v4.z = tfr(v4.z); v4.w = tfr(v4.w);
            *(float4*)(wts + o * 68 + kv * 4) = v4;
        }
        __syncthreads();
        #pragma unroll
        for (int kk = 0; kk < 8; kk++) {
            int kg = it * 64 + kk * 8;
            int ks0 = kk * 8;
            float a[2][4];
            #pragma unroll
            for (int mt = 0; mt < 2; mt++) {
                a[mt][0] = xsm[(m0 + mt * 16 + row) * 260 + kg + quad];
                a[mt][1] = xsm[(m0 + mt * 16 + row + 8) * 260 + kg + quad];
                a[mt][2] = xsm[(m0 + mt * 16 + row) * 260 + kg + quad + 4];
                a[mt][3] = xsm[(m0 + mt * 16 + row + 8) * 260 + kg + quad + 4];
            }
            #pragma unroll
            for (int nt = 0; nt < 4; nt++) {
                float b0 = wts[(n0 + nt * 8 + row) * 68 + ks0 + quad];
                float b1 = wts[(n0 + nt * 8 + row) * 68 + ks0 + quad + 4];
                mma_tf32(acc[0][nt], a[0][0], a[0][1], a[0][2], a[0][3], b0, b1);
                mma_tf32(acc[1][nt], a[1][0], a[1][1], a[1][2], a[1][3], b0, b1);
            }
        }
    }
    // bias + exact GELU -> y1s[p][o], pre-rounded
    #pragma unroll
    for (int mt = 0; mt < 2; mt++) {
        #pragma unroll
        for (int nt = 0; nt < 4; nt++) {
            int col = n0 + nt * 8 + 2 * quad;
            float bb0 = b1[col], bb1 = b1[col + 1];
            int r = m0 + mt * 16 + row;
            float v0 = acc[mt][nt][0] + bb0;
            float v1 = acc[mt][nt][1] + bb1;
            float v2 = acc[mt][nt][2] + bb0;
            float v3 = acc[mt][nt][3] + bb1;
            y1s[r * 260 + col]           = tfr(0.5f * v0 * (1.0f + erff(v0 * 0.70710678118654752f)));
            y1s[r * 260 + col + 1]       = tfr(0.5f * v1 * (1.0f + erff(v1 * 0.70710678118654752f)));
            y1s[(r + 8) * 260 + col]     = tfr(0.5f * v2 * (1.0f + erff(v2 * 0.70710678118654752f)));
            y1s[(r + 8) * 260 + col + 1] = tfr(0.5f * v3 * (1.0f + erff(v3 * 0.70710678118654752f)));
        }
    }
    __syncthreads();

    // ---- GEMM2: OUT(64x128) = Y1 @ W2^T : m(4x16) x n(4x32) ----
    int m0b = (warp & 3) * 16;
    int n0b = (warp >> 2) * 32;
    float ac2[4][4] = {};
    for (int it = 0; it < 4; it++) {
        for (int idx = tid; idx < 128 * 16; idx += 512) {
            int o = idx >> 4, kv = idx & 15;
            float4 v4 = *(const float4*)(w2 + (size_t)o * HID_ + it * 64 + kv * 4);
            v4.x = tfr(v4.x); v4.y = tfr(v4.y); v4.z = tfr(v4.z); v4.w = tfr(v4.w);
            *(float4*)(wts + o * 68 + kv * 4) = v4;
        }
        __syncthreads();
        #pragma unroll
        for (int kk = 0; kk < 8; kk++) {
            int kg = it * 64 + kk * 8;
            int ks0 = kk * 8;
            float a0 = y1s[(m0b + row) * 260 + kg + quad];
            float a1 = y1s[(m0b + row + 8) * 260 + kg + quad];
            float a2 = y1s[(m0b + row) * 260 + kg + quad + 4];
            float a3 = y1s[(m0b + row + 8) * 260 + kg + quad + 4];
            #pragma unroll
            for (int nt = 0; nt < 4; nt++) {
                float b0 = wts[(n0b + nt * 8 + row) * 68 + ks0 + quad];
                float b1 = wts[(n0b + nt * 8 + row) * 68 + ks0 + quad + 4];
                mma_tf32(ac2[nt], a0, a1, a2, a3, b0, b1);
            }
        }
        __syncthreads();
    }

    // ---- epilogue: + b2, write (bs, o, l) ----
    float* og = out + (size_t)bs * OUTC_ * L_;
    int l = l0 + m0b + row;
    #pragma unroll
    for (int nt = 0; nt < 4; nt++) {
        int col = n0b + nt * 8 + 2 * quad;
        float bb0 = b2[col], bb1 = b2[col + 1];
        og[(size_t)col * L_ + l]           = ac2[nt][0] + bb0;
        og[(size_t)(col + 1) * L_ + l]     = ac2[nt][1] + bb1;
        og[(size_t)col * L_ + l + 8]       = ac2[nt][2] + bb0;
        og[(size_t)(col + 1) * L_ + l + 8] = ac2[nt][3] + bb1;
    }
}

// ---------------- launch ----------------
extern "C" void kernel_launch(void* const* d_in, const int* in_sizes, int n_in,
                              void* d_out, int out_size) {
    const float* x      = (const float*)d_in[0];
    const float* qk_w   = (const float*)d_in[1];
    const float* v_w    = (const float*)d_in[2];
    const float* cpb_w1 = (const float*)d_in[3];
    const float* cpb_b1 = (const float*)d_in[4];
    const float* cpb_w2 = (const float*)d_in[5];
    const float* sa_b   = (const float*)d_in[6];
    const float* mlp_w1 = (const float*)d_in[7];
    const float* mlp_b1 = (const float*)d_in[8];
    const float* mlp_w2 = (const float*)d_in[9];
    const float* mlp_b2 = (const float*)d_in[10];
    float* out = (float*)d_out;

    const int SMEM_QKV = (128 * 72 + 64 * 132 + 64 * 68) * 4;                 // 88064
    const int SMEM_ATT = (64 * 68 * 2 + 64 * 136 + 64 * 580) * 4;             // 218112
    const int SMEM_MLP = (64 * 260 + 256 * 68 + 64 * 260) * 4;                // 202752

    cudaFuncSetAttribute(qkv_kernel,  cudaFuncAttributeMaxDynamicSharedMemorySize, SMEM_QKV);
    cudaFuncSetAttribute(attn_kernel, cudaFuncAttributeMaxDynamicSharedMemorySize, SMEM_ATT);
    cudaFuncSetAttribute(mlp_kernel,  cudaFuncAttributeMaxDynamicSharedMemorySize, SMEM_MLP);

    cpb_bias_kernel<<<(L_ * L_) / 256, 256>>>(cpb_w1, cpb_b1, cpb_w2);
    qkv_kernel<<<dim3(9, BS_), 256, SMEM_QKV>>>(x, qk_w, v_w);
    attn_kernel<<<dim3(9, BS_ * HEADS_), 512, SMEM_ATT>>>(sa_b);
    mlp_kernel<<<BS_ * 9, 512, SMEM_MLP>>>(mlp_w1, mlp_b1, mlp_w2, mlp_b2, out);
}

// round 5
// speedup vs baseline: 3.2031x; 1.0244x over previous
#include <cuda_runtime.h>
#include <cuda_bf16.h>
#include <math.h>

#define B_     2
#define S_     32
#define BS_    64
#define C_     128
#define HGT    24
#define WID    24
#define L_     576
#define HEADS_ 2
#define QKD_   64
#define VD_    128
#define HID_   256
#define OUTC_  128

// ---------------- scratch (static device globals; no allocation) ----------------
__device__ float g_bias[HEADS_ * L_ * L_];            // (head, i, j)  fp32, true order
__device__ float g_q[BS_ * HEADS_ * L_ * QKD_];       // [bs,h][l][d-interleaved], tf32
__device__ float g_k[BS_ * HEADS_ * L_ * QKD_];       // [bs,h][l][d-interleaved], tf32
__device__ float g_v[BS_ * HEADS_ * VD_ * L_];        // [bs,h][d][l-interleaved], tf32
__device__ float g_att[BS_ * L_ * HID_];              // [bs][l][ch-interleaved], tf32
// pre-permuted + tf32-rounded weights (k-dim interleaved within 8-blocks)
__device__ float g_wqk[2 * C_ * C_];                  // 256 x 128
__device__ float g_wv [HID_ * C_];                    // 256 x 128
__device__ float g_w1p[HID_ * HID_];                  // 256 x 256
__device__ float g_w2p[OUTC_ * HID_];                 // 128 x 256

// ---------------- helpers ----------------
__device__ __forceinline__ int perm8(int i) {
    return (i & ~7) | (((i & 3) << 1) | ((i >> 2) & 1));
}
__device__ __forceinline__ unsigned f2tf(float f) {
    unsigned r;
    asm("cvt.rna.tf32.f32 %0, %1;" : "=r"(r) : "f"(f));
    return r;
}
__device__ __forceinline__ float tfr(float f) { return __uint_as_float(f2tf(f)); }
__device__ __forceinline__ void mma_tf32(float c[4],
                                         float a0, float a1, float a2, float a3,
                                         float b0, float b1) {
    asm volatile(
        "mma.sync.aligned.m16n8k8.row.col.f32.tf32.tf32.f32 "
        "{%0,%1,%2,%3}, {%4,%5,%6,%7}, {%8,%9}, {%0,%1,%2,%3};"
        : "+f"(c[0]), "+f"(c[1]), "+f"(c[2]), "+f"(c[3])
        : "r"(__float_as_uint(a0)), "r"(__float_as_uint(a1)),
          "r"(__float_as_uint(a2)), "r"(__float_as_uint(a3)),
          "r"(__float_as_uint(b0)), "r"(__float_as_uint(b1)));
}

// ---------------- kernel 0: weight prep (permute k within 8-blocks + tf32 round) ----------------
__global__ void prep_kernel(const float* __restrict__ qk_w, const float* __restrict__ v_w,
                            const float* __restrict__ w1, const float* __restrict__ w2) {
    int idx = blockIdx.x * 256 + threadIdx.x;     // 0 .. 163839
    if (idx < 32768) {
        int o = idx >> 7, k = idx & 127;
        g_wqk[(o << 7) | perm8(k)] = tfr(qk_w[idx]);
    } else if (idx < 65536) {
        int j = idx - 32768; int o = j >> 7, k = j & 127;
        g_wv[(o << 7) | perm8(k)] = tfr(v_w[j]);
    } else if (idx < 131072) {
        int j = idx - 65536; int o = j >> 8, k = j & 255;
        g_w1p[(o << 8) | perm8(k)] = tfr(w1[j]);
    } else {
        int j = idx - 131072; int o = j >> 8, k = j & 255;
        g_w2p[(o << 8) | perm8(k)] = tfr(w2[j]);
    }
}

// ---------------- kernel 1: continuous relative position bias ----------------
__global__ void cpb_bias_kernel(const float* __restrict__ w1,
                                const float* __restrict__ b1,
                                const float* __restrict__ w2) {
    __shared__ float s_w1[256];
    __shared__ float s_b1[128];
    __shared__ float s_w2[256];
    int tid = threadIdx.x;
    s_w1[tid] = w1[tid];
    if (tid < 128) s_b1[tid] = b1[tid];
    s_w2[tid] = w2[tid];
    __syncthreads();

    int idx = blockIdx.x * 256 + tid;      // < 576*576
    int i = idx / L_, j = idx % L_;
    int yi = i / WID, xi = i % WID;
    int yj = j / WID, xj = j % WID;
    float ry = (float)(yi - yj) * (8.0f / 23.0f);
    float rx = (float)(xi - xj) * (8.0f / 23.0f);
    ry = copysignf(log2f(1.0f + fabsf(ry)) * (1.0f / 3.0f), ry);
    rx = copysignf(log2f(1.0f + fabsf(rx)) * (1.0f / 3.0f), rx);

    float acc0 = 0.f, acc1 = 0.f;
    #pragma unroll 4
    for (int k = 0; k < 128; k++) {
        float h = fmaxf(0.f, ry * s_w1[2 * k] + rx * s_w1[2 * k + 1] + s_b1[k]);
        acc0 += h * s_w2[k];
        acc1 += h * s_w2[128 + k];
    }
    g_bias[idx] = acc0;
    g_bias[L_ * L_ + idx] = acc1;
}

// ---------------- kernel 2: QKV projection, tf32 mma ----------------
// Block: (l-tile 64, bs). 256 threads = 8 warps.
// smem: xs[128][72] (true-c rows, l cols), ws[64][136] (k-interleaved), outs[64][72]
__global__ void qkv_kernel(const float* __restrict__ x) {
    int bs = blockIdx.y;
    int l0 = blockIdx.x * 64;
    extern __shared__ float sm[];
    float* xs   = sm;                   // 128*72
    float* ws   = xs + 128 * 72;        // 64*136
    float* outs = ws + 64 * 136;        // 64*72

    int tid = threadIdx.x;
    const float* xb = x + (size_t)bs * C_ * L_;
    for (int idx = tid; idx < 128 * 16; idx += 256) {
        int c = idx >> 4, lv = idx & 15;
        float4 v4 = *(const float4*)(xb + (size_t)c * L_ + l0 + lv * 4);
        v4.x = tfr(v4.x); v4.y = tfr(v4.y); v4.z = tfr(v4.z); v4.w = tfr(v4.w);
        *(float4*)(xs + c * 72 + lv * 4) = v4;
    }

    int warp = tid >> 5, lane = tid & 31;
    int row = lane >> 2, quad = lane & 3;
    int m0 = (warp & 3) * 16;           // o within chunk
    int n0 = (warp >> 2) * 32;          // l within tile

    for (int ot = 0; ot < 8; ot++) {
        const float* wsrc = (ot < 4) ? g_wqk + (size_t)ot * 64 * C_
                                     : g_wv  + (size_t)(ot - 4) * 64 * C_;
        __syncthreads();
        for (int idx = tid; idx < 64 * 32; idx += 256) {
            int o = idx >> 5, kv = idx & 31;
            *(float4*)(ws + o * 136 + kv * 4) = *(const float4*)(wsrc + (size_t)o * C_ + kv * 4);
        }
        __syncthreads();

        float acc[4][4] = {};
        #pragma unroll
        for (int kk = 0; kk < 16; kk++) {
            int k0 = kk * 8;
            float2 aA = *(float2*)(ws + (m0 + row) * 136 + k0 + 2 * quad);      // a0,a2
            float2 aB = *(float2*)(ws + (m0 + row + 8) * 136 + k0 + 2 * quad);  // a1,a3
            #pragma unroll
            for (int nt = 0; nt < 4; nt++) {
                int n = n0 + nt * 8;
                float b0 = xs[(k0 + quad) * 72 + n + row];
                float b1 = xs[(k0 + quad + 4) * 72 + n + row];
                mma_tf32(acc[nt], aA.x, aB.x, aA.y, aB.y, b0, b1);
            }
        }

        if (ot < 4) {
            // Q/K: outs[l][perm(d)]
            int po0 = perm8(m0 + row), po1 = perm8(m0 + row + 8);
            #pragma unroll
            for (int nt = 0; nt < 4; nt++) {
                int n = n0 + nt * 8 + 2 * quad;
                outs[n * 72 + po0]       = tfr(acc[nt][0]);
                outs[(n + 1) * 72 + po0] = tfr(acc[nt][1]);
                outs[n * 72 + po1]       = tfr(acc[nt][2]);
                outs[(n + 1) * 72 + po1] = tfr(acc[nt][3]);
            }
            __syncthreads();
            float* dst = (ot < 2) ? g_q + (size_t)(bs * 2 + ot) * L_ * QKD_
                                  : g_k + (size_t)(bs * 2 + ot - 2) * L_ * QKD_;
            for (int idx = tid; idx < 64 * 16; idx += 256) {
                int l = idx >> 4, j = idx & 15;
                *(float4*)(dst + (size_t)(l0 + l) * QKD_ + j * 4) =
                    *(float4*)(outs + l * 72 + j * 4);
            }
        } else {
            // V: outs[d][perm(l)]  (transposed, l-interleaved)
            #pragma unroll
            for (int nt = 0; nt < 4; nt++) {
                int cl = n0 + nt * 8 + 2 * quad;
                int p0 = perm8(cl), p1 = perm8(cl + 1);
                outs[(m0 + row) * 72 + p0]     = tfr(acc[nt][0]);
                outs[(m0 + row) * 72 + p1]     = tfr(acc[nt][1]);
                outs[(m0 + row + 8) * 72 + p0] = tfr(acc[nt][2]);
                outs[(m0 + row + 8) * 72 + p1] = tfr(acc[nt][3]);
            }
            __syncthreads();
            int o2 = (ot - 4) * 64;
            int head = o2 >> 7, dof = o2 & 127;
            float* dst = g_v + (size_t)(bs * 2 + head) * VD_ * L_;
            for (int idx = tid; idx < 64 * 16; idx += 256) {
                int o = idx >> 4, j = idx & 15;
                *(float4*)(dst + (size_t)(dof + o) * L_ + l0 + j * 4) =
                    *(float4*)(outs + o * 72 + j * 4);
            }
        }
    }
}

// ---------------- kernel 3: fused attention, tf32 mma, 512 threads = 16 warps ----------------
// smem: qs[64][72], ks[64][72], vt[128][72], sc[64][584]
__global__ void attn_kernel(const float* __restrict__ sa_bias) {
    int qt = blockIdx.x;              // 0..8
    int bh = blockIdx.y;              // 0..127
    int bs = bh >> 1, head = bh & 1;
    int q0 = qt * 64;

    extern __shared__ float sm[];
    float* qs = sm;                    // 64*72
    float* ks = qs + 64 * 72;          // 64*72
    float* vt = ks + 64 * 72;          // 128*72
    float* sc = vt + 128 * 72;         // 64*584

    const float* qg = g_q + (size_t)(bs * 2 + head) * L_ * QKD_;
    const float* kg = g_k + (size_t)(bs * 2 + head) * L_ * QKD_;
    const float* vg = g_v + (size_t)(bs * 2 + head) * VD_ * L_;
    const float* bg = g_bias + (size_t)head * L_ * L_;

    int tid = threadIdx.x;
    int warp = tid >> 5, lane = tid & 31;
    int row = lane >> 2, quad = lane & 3;
    int m0 = (warp & 3) * 16;          // q rows

    // load q tile [64][64] (d-interleaved in gmem, verbatim copy)
    for (int idx = tid; idx < 64 * 16; idx += 512) {
        int l = idx >> 4, dv = idx & 15;
        *(float4*)(qs + l * 72 + dv * 4) = *(const float4*)(qg + (size_t)(q0 + l) * QKD_ + dv * 4);
    }

    // ---- scores: 16 warps cover 64x64 as m(4x16) x n(4x16) ----
    {
        int n0 = (warp >> 2) * 16;
        for (int kt = 0; kt < 9; kt++) {
            __syncthreads();
            for (int idx = tid; idx < 64 * 16; idx += 512) {
                int l = idx >> 4, dv = idx & 15;
                *(float4*)(ks + l * 72 + dv * 4) =
                    *(const float4*)(kg + (size_t)(kt * 64 + l) * QKD_ + dv * 4);
            }
            __syncthreads();

            float acc[2][4] = {};
            #pragma unroll
            for (int kk = 0; kk < 8; kk++) {
                int k0 = kk * 8;
                float2 aA = *(float2*)(qs + (m0 + row) * 72 + k0 + 2 * quad);
                float2 aB = *(float2*)(qs + (m0 + row + 8) * 72 + k0 + 2 * quad);
                #pragma unroll
                for (int nt = 0; nt < 2; nt++) {
                    float2 bv = *(float2*)(ks + (n0 + nt * 8 + row) * 72 + k0 + 2 * quad);
                    mma_tf32(acc[nt], aA.x, aB.x, aA.y, aB.y, bv.x, bv.y);
                }
            }

            int r0 = q0 + m0 + row;
            #pragma unroll
            for (int nt = 0; nt < 2; nt++) {
                int cl = n0 + nt * 8 + 2 * quad;          // local col (even)
                int p0 = kt * 64 + perm8(cl), p1 = kt * 64 + perm8(cl + 1);
                int ct = kt * 64 + cl;                    // true col
                sc[(m0 + row) * 584 + p0]     = acc[nt][0] * 0.125f + bg[(size_t)r0 * L_ + ct];
                sc[(m0 + row) * 584 + p1]     = acc[nt][1] * 0.125f + bg[(size_t)r0 * L_ + ct + 1];
                sc[(m0 + row + 8) * 584 + p0] = acc[nt][2] * 0.125f + bg[(size_t)(r0 + 8) * L_ + ct];
                sc[(m0 + row + 8) * 584 + p1] = acc[nt][3] * 0.125f + bg[(size_t)(r0 + 8) * L_ + ct + 1];
            }
        }
    }
    __syncthreads();

    // ---- softmax: 16 warps x 4 rows (permutation-invariant), store tf32-rounded probs ----
    for (int rr = 0; rr < 4; rr++) {
        int r = warp * 4 + rr;
        float mx = -1e30f;
        for (int i = lane; i < L_; i += 32) mx = fmaxf(mx, sc[r * 584 + i]);
        #pragma unroll
        for (int off = 16; off > 0; off >>= 1)
            mx = fmaxf(mx, __shfl_xor_sync(0xffffffffu, mx, off));
        float sum = 0.f;
        for (int i = lane; i < L_; i += 32) {
            float e = __expf(sc[r * 584 + i] - mx);
            sc[r * 584 + i] = e;
            sum += e;
        }
        #pragma unroll
        for (int off = 16; off > 0; off >>= 1)
            sum += __shfl_xor_sync(0xffffffffu, sum, off);
        float inv = 1.0f / sum;
        for (int i = lane; i < L_; i += 32) sc[r * 584 + i] = tfr(sc[r * 584 + i] * inv);
    }
    __syncthreads();

    // ---- AV: 64x128 as m(4x16) x n(4x32); V staged [d][l-interleaved] ----
    {
        int n0 = (warp >> 2) * 32;
        float oac[4][4] = {};
        for (int vti = 0; vti < 9; vti++) {
            int s0 = vti * 64;
            for (int idx = tid; idx < 128 * 16; idx += 512) {
                int d = idx >> 4, j = idx & 15;
                *(float4*)(vt + d * 72 + j * 4) =
                    *(const float4*)(vg + (size_t)d * L_ + s0 + j * 4);
            }
            __syncthreads();
            #pragma unroll
            for (int kk = 0; kk < 8; kk++) {
                int kb = kk * 8;
                float2 aA = *(float2*)(sc + (m0 + row) * 584 + s0 + kb + 2 * quad);
                float2 aB = *(float2*)(sc + (m0 + row + 8) * 584 + s0 + kb + 2 * quad);
                #pragma unroll
                for (int nt = 0; nt < 4; nt++) {
                    float2 bv = *(float2*)(vt + (n0 + nt * 8 + row) * 72 + kb + 2 * quad);
                    mma_tf32(oac[nt], aA.x, aB.x, aA.y, aB.y, bv.x, bv.y);
                }
            }
            __syncthreads();
        }

        // ---- write out + sa_bias, ch-interleaved + tf32-rounded for the MLP ----
        float* og = g_att + (size_t)bs * L_ * HID_;
        int l = q0 + m0 + row;
        #pragma unroll
        for (int nt = 0; nt < 4; nt++) {
            int ch = head * 128 + n0 + nt * 8 + 2 * quad;
            int pc0 = perm8(ch), pc1 = perm8(ch + 1);
            float sb0 = sa_bias[ch], sb1 = sa_bias[ch + 1];
            og[(size_t)l * HID_ + pc0]       = tfr(oac[nt][0] + sb0);
            og[(size_t)l * HID_ + pc1]       = tfr(oac[nt][1] + sb1);
            og[(size_t)(l + 8) * HID_ + pc0] = tfr(oac[nt][2] + sb0);
            og[(size_t)(l + 8) * HID_ + pc1] = tfr(oac[nt][3] + sb1);
        }
    }
}

// ---------------- kernel 4: MLP (tf32 mma), 512 threads = 16 warps ----------------
// smem: xsm[64][264], wts[256][72], y1s[64][264]
__global__ void mlp_kernel(const float* __restrict__ b1, const float* __restrict__ b2,
                           float* __restrict__ out) {
    int blk = blockIdx.x;                // 0..575
    int bs = blk / 9;
    int l0 = (blk % 9) * 64;
    extern __shared__ float sm[];
    float* xsm = sm;                     // 64*264
    float* wts = xsm + 64 * 264;         // 256*72
    float* y1s = wts + 256 * 72;         // 64*264

    int tid = threadIdx.x;
    int warp = tid >> 5, lane = tid & 31;
    int row = lane >> 2, quad = lane & 3;

    const float* ag = g_att + ((size_t)bs * L_ + l0) * HID_;
    for (int idx = tid; idx < 64 * 64; idx += 512) {
        int p = idx >> 6, iv = idx & 63;
        *(float4*)(xsm + p * 264 + iv * 4) = *(const float4*)(ag + (size_t)p * HID_ + iv * 4);
    }

    // ---- GEMM1: Y1(64x256) = X @ W1^T : warp tile m32 x n32 ----
    int m0 = (warp & 1) * 32;
    int n0 = (warp >> 1) * 32;
    float acc[2][4][4] = {};
    for (int it = 0; it < 4; it++) {
        __syncthreads();
        for (int idx = tid; idx < 256 * 16; idx += 512) {
            int o = idx >> 4, kv = idx & 15;
            *(float4*)(wts + o * 72 + kv * 4) = *(const float4*)(g_w1p + (size_t)o * HID_ + it * 64 + kv * 4);
        }
        __syncthreads();
        #pragma unroll
        for (int kk = 0; kk < 8; kk++) {
            int kg = it * 64 + kk * 8;
            int kb = kk * 8;
            float2 aA[2], aB[2];
            #pragma unroll
            for (int mt = 0; mt < 2; mt++) {
                aA[mt] = *(float2*)(xsm + (m0 + mt * 16 + row) * 264 + kg + 2 * quad);
                aB[mt] = *(float2*)(xsm + (m0 + mt * 16 + row + 8) * 264 + kg + 2 * quad);
            }
            #pragma unroll
            for (int nt = 0; nt < 4; nt++) {
                float2 bv = *(float2*)(wts + (n0 + nt * 8 + row) * 72 + kb + 2 * quad);
                mma_tf32(acc[0][nt], aA[0].x, aB[0].x, aA[0].y, aB[0].y, bv.x, bv.y);
                mma_tf32(acc[1][nt], aA[1].x, aB[1].x, aA[1].y, aB[1].y, bv.x, bv.y);
            }
        }
    }
    // bias + exact GELU -> y1s[p][perm(o)], tf32-rounded
    #pragma unroll
    for (int mt = 0; mt < 2; mt++) {
        #pragma unroll
        for (int nt = 0; nt < 4; nt++) {
            int col = n0 + nt * 8 + 2 * quad;
            int p0 = perm8(col), p1 = perm8(col + 1);
            float bb0 = b1[col], bb1 = b1[col + 1];
            int r = m0 + mt * 16 + row;
            float v0 = acc[mt][nt][0] + bb0;
            float v1 = acc[mt][nt][1] + bb1;
            float v2 = acc[mt][nt][2] + bb0;
            float v3 = acc[mt][nt][3] + bb1;
            y1s[r * 264 + p0]       = tfr(0.5f * v0 * (1.0f + erff(v0 * 0.70710678118654752f)));
            y1s[r * 264 + p1]       = tfr(0.5f * v1 * (1.0f + erff(v1 * 0.70710678118654752f)));
            y1s[(r + 8) * 264 + p0] = tfr(0.5f * v2 * (1.0f + erff(v2 * 0.70710678118654752f)));
            y1s[(r + 8) * 264 + p1] = tfr(0.5f * v3 * (1.0f + erff(v3 * 0.70710678118654752f)));
        }
    }
    __syncthreads();

    // ---- GEMM2: OUT(64x128) = Y1 @ W2^T : warp tile m16 x n32 ----
    int m0b = (warp & 3) * 16;
    int n0b = (warp >> 2) * 32;
    float ac2[4][4] = {};
    for (int it = 0; it < 4; it++) {
        for (int idx = tid; idx < 128 * 16; idx += 512) {
            int o = idx >> 4, kv = idx & 15;
            *(float4*)(wts + o * 72 + kv * 4) = *(const float4*)(g_w2p + (size_t)o * HID_ + it * 64 + kv * 4);
        }
        __syncthreads();
        #pragma unroll
        for (int kk = 0; kk < 8; kk++) {
            int kg = it * 64 + kk * 8;
            int kb = kk * 8;
            float2 aA = *(float2*)(y1s + (m0b + row) * 264 + kg + 2 * quad);
            float2 aB = *(float2*)(y1s + (m0b + row + 8) * 264 + kg + 2 * quad);
            #pragma unroll
            for (int nt = 0; nt < 4; nt++) {
                float2 bv = *(float2*)(wts + (n0b + nt * 8 + row) * 72 + kb + 2 * quad);
                mma_tf32(ac2[nt], aA.x, aB.x, aA.y, aB.y, bv.x, bv.y);
            }
        }
        __syncthreads();
    }

    // ---- epilogue: + b2, write (bs, o, l) ----
    float* og = out + (size_t)bs * OUTC_ * L_;
    int l = l0 + m0b + row;
    #pragma unroll
    for (int nt = 0; nt < 4; nt++) {
        int col = n0b + nt * 8 + 2 * quad;
        float bb0 = b2[col], bb1 = b2[col + 1];
        og[(size_t)col * L_ + l]           = ac2[nt][0] + bb0;
        og[(size_t)(col + 1) * L_ + l]     = ac2[nt][1] + bb1;
        og[(size_t)col * L_ + l + 8]       = ac2[nt][2] + bb0;
        og[(size_t)(col + 1) * L_ + l + 8] = ac2[nt][3] + bb1;
    }
}

// ---------------- launch ----------------
extern "C" void kernel_launch(void* const* d_in, const int* in_sizes, int n_in,
                              void* d_out, int out_size) {
    const float* x      = (const float*)d_in[0];
    const float* qk_w   = (const float*)d_in[1];
    const float* v_w    = (const float*)d_in[2];
    const float* cpb_w1 = (const float*)d_in[3];
    const float* cpb_b1 = (const float*)d_in[4];
    const float* cpb_w2 = (const float*)d_in[5];
    const float* sa_b   = (const float*)d_in[6];
    const float* mlp_b1 = (const float*)d_in[8];
    const float* mlp_b2 = (const float*)d_in[10];
    float* out = (float*)d_out;

    const int SMEM_QKV = (128 * 72 + 64 * 136 + 64 * 72) * 4;                  // 90112
    const int SMEM_ATT = (64 * 72 * 2 + 128 * 72 + 64 * 584) * 4;              // 223232
    const int SMEM_MLP = (64 * 264 * 2 + 256 * 72) * 4;                        // 208896

    cudaFuncSetAttribute(qkv_kernel,  cudaFuncAttributeMaxDynamicSharedMemorySize, SMEM_QKV);
    cudaFuncSetAttribute(attn_kernel, cudaFuncAttributeMaxDynamicSharedMemorySize, SMEM_ATT);
    cudaFuncSetAttribute(mlp_kernel,  cudaFuncAttributeMaxDynamicSharedMemorySize, SMEM_MLP);

    prep_kernel<<<640, 256>>>(qk_w, v_w, (const float*)d_in[7], (const float*)d_in[9]);
    cpb_bias_kernel<<<(L_ * L_) / 256, 256>>>(cpb_w1, cpb_b1, cpb_w2);
    qkv_kernel<<<dim3(9, BS_), 256, SMEM_QKV>>>(x);
    attn_kernel<<<dim3(9, BS_ * HEADS_), 512, SMEM_ATT>>>(sa_b);
    mlp_kernel<<<BS_ * 9, 512, SMEM_MLP>>>(mlp_b1, mlp_b2, out);
}

// round 6
// speedup vs baseline: 3.9912x; 1.2461x over previous
#include <cuda_runtime.h>
#include <cuda_bf16.h>
#include <math.h>

#define B_     2
#define S_     32
#define BS_    64
#define C_     128
#define HGT    24
#define WID    24
#define L_     576
#define HEADS_ 2
#define QKD_   64
#define VD_    128
#define HID_   256
#define OUTC_  128

// ---------------- scratch (static device globals; no allocation) ----------------
__device__ float g_bias[HEADS_ * L_ * L_];            // (head, i, j)  fp32, true order
__device__ float g_q[BS_ * HEADS_ * L_ * QKD_];       // [bs,h][l][d-interleaved], tf32
__device__ float g_k[BS_ * HEADS_ * L_ * QKD_];       // [bs,h][l][d-interleaved], tf32
__device__ float g_v[BS_ * HEADS_ * VD_ * L_];        // [bs,h][d][l-interleaved], tf32
__device__ float g_att[BS_ * L_ * HID_];              // [bs][l][ch-interleaved], tf32
// pre-permuted + tf32-rounded weights (k-dim interleaved within 8-blocks)
__device__ float g_wqk[2 * C_ * C_];                  // 256 x 128
__device__ float g_wv [HID_ * C_];                    // 256 x 128
__device__ float g_w1p[HID_ * HID_];                  // 256 x 256
__device__ float g_w2p[OUTC_ * HID_];                 // 128 x 256

// ---------------- helpers ----------------
__device__ __forceinline__ int perm8(int i) {
    return (i & ~7) | (((i & 3) << 1) | ((i >> 2) & 1));
}
__device__ __forceinline__ unsigned f2tf(float f) {
    unsigned r;
    asm("cvt.rna.tf32.f32 %0, %1;" : "=r"(r) : "f"(f));
    return r;
}
__device__ __forceinline__ float tfr(float f) { return __uint_as_float(f2tf(f)); }
__device__ __forceinline__ void mma_tf32(float c[4],
                                         float a0, float a1, float a2, float a3,
                                         float b0, float b1) {
    asm volatile(
        "mma.sync.aligned.m16n8k8.row.col.f32.tf32.tf32.f32 "
        "{%0,%1,%2,%3}, {%4,%5,%6,%7}, {%8,%9}, {%0,%1,%2,%3};"
        : "+f"(c[0]), "+f"(c[1]), "+f"(c[2]), "+f"(c[3])
        : "r"(__float_as_uint(a0)), "r"(__float_as_uint(a1)),
          "r"(__float_as_uint(a2)), "r"(__float_as_uint(a3)),
          "r"(__float_as_uint(b0)), "r"(__float_as_uint(b1)));
}

// ---------------- kernel 0: weight prep (permute k within 8-blocks + tf32 round) ----------------
__global__ void prep_kernel(const float* __restrict__ qk_w, const float* __restrict__ v_w,
                            const float* __restrict__ w1, const float* __restrict__ w2) {
    int idx = blockIdx.x * 256 + threadIdx.x;     // 0 .. 163839
    if (idx < 32768) {
        int o = idx >> 7, k = idx & 127;
        g_wqk[(o << 7) | perm8(k)] = tfr(qk_w[idx]);
    } else if (idx < 65536) {
        int j = idx - 32768; int o = j >> 7, k = j & 127;
        g_wv[(o << 7) | perm8(k)] = tfr(v_w[j]);
    } else if (idx < 131072) {
        int j = idx - 65536; int o = j >> 8, k = j & 255;
        g_w1p[(o << 8) | perm8(k)] = tfr(w1[j]);
    } else {
        int j = idx - 131072; int o = j >> 8, k = j & 255;
        g_w2p[(o << 8) | perm8(k)] = tfr(w2[j]);
    }
}

// ---------------- kernel 1: continuous relative position bias ----------------
__global__ void cpb_bias_kernel(const float* __restrict__ w1,
                                const float* __restrict__ b1,
                                const float* __restrict__ w2) {
    __shared__ float s_w1[256];
    __shared__ float s_b1[128];
    __shared__ float s_w2[256];
    int tid = threadIdx.x;
    s_w1[tid] = w1[tid];
    if (tid < 128) s_b1[tid] = b1[tid];
    s_w2[tid] = w2[tid];
    __syncthreads();

    int idx = blockIdx.x * 256 + tid;      // < 576*576
    int i = idx / L_, j = idx % L_;
    int yi = i / WID, xi = i % WID;
    int yj = j / WID, xj = j % WID;
    float ry = (float)(yi - yj) * (8.0f / 23.0f);
    float rx = (float)(xi - xj) * (8.0f / 23.0f);
    ry = copysignf(log2f(1.0f + fabsf(ry)) * (1.0f / 3.0f), ry);
    rx = copysignf(log2f(1.0f + fabsf(rx)) * (1.0f / 3.0f), rx);

    float acc0 = 0.f, acc1 = 0.f;
    #pragma unroll 4
    for (int k = 0; k < 128; k++) {
        float h = fmaxf(0.f, ry * s_w1[2 * k] + rx * s_w1[2 * k + 1] + s_b1[k]);
        acc0 += h * s_w2[k];
        acc1 += h * s_w2[128 + k];
    }
    g_bias[idx] = acc0;
    g_bias[L_ * L_ + idx] = acc1;
}

// ---------------- kernel 2: QKV projection, tf32 mma ----------------
// Block: (l-tile 64, bs). 256 threads = 8 warps.
__global__ void qkv_kernel(const float* __restrict__ x) {
    int bs = blockIdx.y;
    int l0 = blockIdx.x * 64;
    extern __shared__ float sm[];
    float* xs   = sm;                   // 128*72
    float* ws   = xs + 128 * 72;        // 64*136
    float* outs = ws + 64 * 136;        // 64*72

    int tid = threadIdx.x;
    const float* xb = x + (size_t)bs * C_ * L_;
    for (int idx = tid; idx < 128 * 16; idx += 256) {
        int c = idx >> 4, lv = idx & 15;
        float4 v4 = *(const float4*)(xb + (size_t)c * L_ + l0 + lv * 4);
        v4.x = tfr(v4.x); v4.y = tfr(v4.y); v4.z = tfr(v4.z); v4.w = tfr(v4.w);
        *(float4*)(xs + c * 72 + lv * 4) = v4;
    }

    int warp = tid >> 5, lane = tid & 31;
    int row = lane >> 2, quad = lane & 3;
    int m0 = (warp & 3) * 16;           // o within chunk
    int n0 = (warp >> 2) * 32;          // l within tile

    for (int ot = 0; ot < 8; ot++) {
        const float* wsrc = (ot < 4) ? g_wqk + (size_t)ot * 64 * C_
                                     : g_wv  + (size_t)(ot - 4) * 64 * C_;
        __syncthreads();
        for (int idx = tid; idx < 64 * 32; idx += 256) {
            int o = idx >> 5, kv = idx & 31;
            *(float4*)(ws + o * 136 + kv * 4) = *(const float4*)(wsrc + (size_t)o * C_ + kv * 4);
        }
        __syncthreads();

        float acc[4][4] = {};
        #pragma unroll
        for (int kk = 0; kk < 16; kk++) {
            int k0 = kk * 8;
            float2 aA = *(float2*)(ws + (m0 + row) * 136 + k0 + 2 * quad);      // a0,a2
            float2 aB = *(float2*)(ws + (m0 + row + 8) * 136 + k0 + 2 * quad);  // a1,a3
            #pragma unroll
            for (int nt = 0; nt < 4; nt++) {
                int n = n0 + nt * 8;
                float b0 = xs[(k0 + quad) * 72 + n + row];
                float b1 = xs[(k0 + quad + 4) * 72 + n + row];
                mma_tf32(acc[nt], aA.x, aB.x, aA.y, aB.y, b0, b1);
            }
        }

        if (ot < 4) {
            // Q/K: outs[l][perm(d)]
            int po0 = perm8(m0 + row), po1 = perm8(m0 + row + 8);
            #pragma unroll
            for (int nt = 0; nt < 4; nt++) {
                int n = n0 + nt * 8 + 2 * quad;
                outs[n * 72 + po0]       = tfr(acc[nt][0]);
                outs[(n + 1) * 72 + po0] = tfr(acc[nt][1]);
                outs[n * 72 + po1]       = tfr(acc[nt][2]);
                outs[(n + 1) * 72 + po1] = tfr(acc[nt][3]);
            }
            __syncthreads();
            float* dst = (ot < 2) ? g_q + (size_t)(bs * 2 + ot) * L_ * QKD_
                                  : g_k + (size_t)(bs * 2 + ot - 2) * L_ * QKD_;
            for (int idx = tid; idx < 64 * 16; idx += 256) {
                int l = idx >> 4, j = idx & 15;
                *(float4*)(dst + (size_t)(l0 + l) * QKD_ + j * 4) =
                    *(float4*)(outs + l * 72 + j * 4);
            }
        } else {
            // V: outs[d][perm(l)]  (transposed, l-interleaved)
            #pragma unroll
            for (int nt = 0; nt < 4; nt++) {
                int cl = n0 + nt * 8 + 2 * quad;
                int p0 = perm8(cl), p1 = perm8(cl + 1);
                outs[(m0 + row) * 72 + p0]     = tfr(acc[nt][0]);
                outs[(m0 + row) * 72 + p1]     = tfr(acc[nt][1]);
                outs[(m0 + row + 8) * 72 + p0] = tfr(acc[nt][2]);
                outs[(m0 + row + 8) * 72 + p1] = tfr(acc[nt][3]);
            }
            __syncthreads();
            int o2 = (ot - 4) * 64;
            int head = o2 >> 7, dof = o2 & 127;
            float* dst = g_v + (size_t)(bs * 2 + head) * VD_ * L_;
            for (int idx = tid; idx < 64 * 16; idx += 256) {
                int o = idx >> 4, j = idx & 15;
                *(float4*)(dst + (size_t)(dof + o) * L_ + l0 + j * 4) =
                    *(float4*)(outs + o * 72 + j * 4);
            }
        }
    }
}

// ---------------- kernel 3: flash attention, tf32 mma, 512 threads, 2 CTAs/SM ----------------
// smem: qs[64][72], ks[64][72], vt[128][72], ps[64][72], mrow/lrow/arow[64]
__global__ void __launch_bounds__(512, 2) attn_kernel(const float* __restrict__ sa_bias) {
    int qt = blockIdx.x;              // 0..8
    int bh = blockIdx.y;              // 0..127
    int bs = bh >> 1, head = bh & 1;
    int q0 = qt * 64;

    extern __shared__ float sm[];
    float* qs   = sm;                  // 64*72
    float* ks   = qs + 64 * 72;        // 64*72
    float* vt   = ks + 64 * 72;        // 128*72
    float* ps   = vt + 128 * 72;       // 64*72
    float* mrow = ps + 64 * 72;        // 64
    float* lrow = mrow + 64;           // 64
    float* arow = lrow + 64;           // 64

    const float* qg = g_q + (size_t)(bs * 2 + head) * L_ * QKD_;
    const float* kg = g_k + (size_t)(bs * 2 + head) * L_ * QKD_;
    const float* vg = g_v + (size_t)(bs * 2 + head) * VD_ * L_;
    const float* bg = g_bias + (size_t)head * L_ * L_;

    int tid = threadIdx.x;
    int warp = tid >> 5, lane = tid & 31;
    int row = lane >> 2, quad = lane & 3;
    int m0  = (warp & 3) * 16;         // q rows
    int n0s = (warp >> 2) * 16;        // score n-tile (64 cols over 4 warps)
    int n0v = (warp >> 2) * 32;        // AV n-tile (128 d over 4 warps)

    // load q tile [64][64] (d-interleaved, verbatim)
    for (int idx = tid; idx < 64 * 16; idx += 512) {
        int l = idx >> 4, dv = idx & 15;
        *(float4*)(qs + l * 72 + dv * 4) = *(const float4*)(qg + (size_t)(q0 + l) * QKD_ + dv * 4);
    }
    if (tid < 64) { mrow[tid] = -1e30f; lrow[tid] = 0.f; }

    float oac[4][4] = {};

    for (int kt = 0; kt < 9; kt++) {
        __syncthreads();   // previous AV done with vt/ps; qs/mrow init visible on kt=0
        // stage K tile [64 keys][64 d]
        for (int idx = tid; idx < 64 * 16; idx += 512) {
            int l = idx >> 4, dv = idx & 15;
            *(float4*)(ks + l * 72 + dv * 4) =
                *(const float4*)(kg + (size_t)(kt * 64 + l) * QKD_ + dv * 4);
        }
        // stage V tile [128 d][64 keys-interleaved]
        for (int idx = tid; idx < 128 * 16; idx += 512) {
            int d = idx >> 4, j = idx & 15;
            *(float4*)(vt + d * 72 + j * 4) =
                *(const float4*)(vg + (size_t)d * L_ + kt * 64 + j * 4);
        }
        __syncthreads();

        // ---- S = Q K^T (16x16 per warp) + bias, raw into ps (perm cols) ----
        float acc[2][4] = {};
        #pragma unroll
        for (int kk = 0; kk < 8; kk++) {
            int k0 = kk * 8;
            float2 aA = *(float2*)(qs + (m0 + row) * 72 + k0 + 2 * quad);
            float2 aB = *(float2*)(qs + (m0 + row + 8) * 72 + k0 + 2 * quad);
            #pragma unroll
            for (int nt = 0; nt < 2; nt++) {
                float2 bv = *(float2*)(ks + (n0s + nt * 8 + row) * 72 + k0 + 2 * quad);
                mma_tf32(acc[nt], aA.x, aB.x, aA.y, aB.y, bv.x, bv.y);
            }
        }
        {
            int r0 = q0 + m0 + row;
            #pragma unroll
            for (int nt = 0; nt < 2; nt++) {
                int cl = n0s + nt * 8 + 2 * quad;
                int p0 = perm8(cl), p1 = perm8(cl + 1);
                int ct = kt * 64 + cl;
                ps[(m0 + row) * 72 + p0]     = acc[nt][0] * 0.125f + bg[(size_t)r0 * L_ + ct];
                ps[(m0 + row) * 72 + p1]     = acc[nt][1] * 0.125f + bg[(size_t)r0 * L_ + ct + 1];
                ps[(m0 + row + 8) * 72 + p0] = acc[nt][2] * 0.125f + bg[(size_t)(r0 + 8) * L_ + ct];
                ps[(m0 + row + 8) * 72 + p1] = acc[nt][3] * 0.125f + bg[(size_t)(r0 + 8) * L_ + ct + 1];
            }
        }
        __syncthreads();

        // ---- online softmax update: warp owns rows warp*4 .. warp*4+3 ----
        #pragma unroll
        for (int rr = 0; rr < 4; rr++) {
            int r = warp * 4 + rr;
            float2 pv = *(float2*)(ps + r * 72 + 2 * lane);
            float tmax = fmaxf(pv.x, pv.y);
            #pragma unroll
            for (int off = 16; off > 0; off >>= 1)
                tmax = fmaxf(tmax, __shfl_xor_sync(0xffffffffu, tmax, off));
            float mo = mrow[r];
            float mn = fmaxf(mo, tmax);
            float e0 = __expf(pv.x - mn);
            float e1 = __expf(pv.y - mn);
            float2 pr; pr.x = tfr(e0); pr.y = tfr(e1);
            *(float2*)(ps + r * 72 + 2 * lane) = pr;
            float ss = e0 + e1;
            #pragma unroll
            for (int off = 16; off > 0; off >>= 1)
                ss += __shfl_xor_sync(0xffffffffu, ss, off);
            if (lane == 0) {
                float al = __expf(mo - mn);
                arow[r] = al;
                mrow[r] = mn;
                lrow[r] = al * lrow[r] + ss;
            }
        }
        __syncthreads();

        // ---- AV: rescale + accumulate (m16 x n32 per warp) ----
        float al0 = arow[m0 + row], al1 = arow[m0 + row + 8];
        #pragma unroll
        for (int nt = 0; nt < 4; nt++) {
            oac[nt][0] *= al0; oac[nt][1] *= al0;
            oac[nt][2] *= al1; oac[nt][3] *= al1;
        }
        #pragma unroll
        for (int kk = 0; kk < 8; kk++) {
            int kb = kk * 8;
            float2 aA = *(float2*)(ps + (m0 + row) * 72 + kb + 2 * quad);
            float2 aB = *(float2*)(ps + (m0 + row + 8) * 72 + kb + 2 * quad);
            #pragma unroll
            for (int nt = 0; nt < 4; nt++) {
                float2 bv = *(float2*)(vt + (n0v + nt * 8 + row) * 72 + kb + 2 * quad);
                mma_tf32(oac[nt], aA.x, aB.x, aA.y, aB.y, bv.x, bv.y);
            }
        }
    }

    // ---- epilogue: normalize, + sa_bias, ch-interleaved tf32 write ----
    float inv0 = 1.0f / lrow[m0 + row];
    float inv1 = 1.0f / lrow[m0 + row + 8];
    float* og = g_att + (size_t)bs * L_ * HID_;
    int l = q0 + m0 + row;
    #pragma unroll
    for (int nt = 0; nt < 4; nt++) {
        int ch = head * 128 + n0v + nt * 8 + 2 * quad;
        int pc0 = perm8(ch), pc1 = perm8(ch + 1);
        float sb0 = sa_bias[ch], sb1 = sa_bias[ch + 1];
        og[(size_t)l * HID_ + pc0]       = tfr(oac[nt][0] * inv0 + sb0);
        og[(size_t)l * HID_ + pc1]       = tfr(oac[nt][1] * inv0 + sb1);
        og[(size_t)(l + 8) * HID_ + pc0] = tfr(oac[nt][2] * inv1 + sb0);
        og[(size_t)(l + 8) * HID_ + pc1] = tfr(oac[nt][3] * inv1 + sb1);
    }
}

// ---------------- kernel 4: MLP (tf32 mma), 512 threads = 16 warps ----------------
// smem: xsm[64][264], wts[256][72], y1s[64][264]
__global__ void mlp_kernel(const float* __restrict__ b1, const float* __restrict__ b2,
                           float* __restrict__ out) {
    int blk = blockIdx.x;                // 0..575
    int bs = blk / 9;
    int l0 = (blk % 9) * 64;
    extern __shared__ float sm[];
    float* xsm = sm;                     // 64*264
    float* wts = xsm + 64 * 264;         // 256*72
    float* y1s = wts + 256 * 72;         // 64*264

    int tid = threadIdx.x;
    int warp = tid >> 5, lane = tid & 31;
    int row = lane >> 2, quad = lane & 3;

    const float* ag = g_att + ((size_t)bs * L_ + l0) * HID_;
    for (int idx = tid; idx < 64 * 64; idx += 512) {
        int p = idx >> 6, iv = idx & 63;
        *(float4*)(xsm + p * 264 + iv * 4) = *(const float4*)(ag + (size_t)p * HID_ + iv * 4);
    }

    // ---- GEMM1: Y1(64x256) = X @ W1^T : warp tile m32 x n32 ----
    int m0 = (warp & 1) * 32;
    int n0 = (warp >> 1) * 32;
    float acc[2][4][4] = {};
    for (int it = 0; it < 4; it++) {
        __syncthreads();
        for (int idx = tid; idx < 256 * 16; idx += 512) {
            int o = idx >> 4, kv = idx & 15;
            *(float4*)(wts + o * 72 + kv * 4) = *(const float4*)(g_w1p + (size_t)o * HID_ + it * 64 + kv * 4);
        }
        __syncthreads();
        #pragma unroll
        for (int kk = 0; kk < 8; kk++) {
            int kg = it * 64 + kk * 8;
            int kb = kk * 8;
            float2 aA[2], aB[2];
            #pragma unroll
            for (int mt = 0; mt < 2; mt++) {
                aA[mt] = *(float2*)(xsm + (m0 + mt * 16 + row) * 264 + kg + 2 * quad);
                aB[mt] = *(float2*)(xsm + (m0 + mt * 16 + row + 8) * 264 + kg + 2 * quad);
            }
            #pragma unroll
            for (int nt = 0; nt < 4; nt++) {
                float2 bv = *(float2*)(wts + (n0 + nt * 8 + row) * 72 + kb + 2 * quad);
                mma_tf32(acc[0][nt], aA[0].x, aB[0].x, aA[0].y, aB[0].y, bv.x, bv.y);
                mma_tf32(acc[1][nt], aA[1].x, aB[1].x, aA[1].y, aB[1].y, bv.x, bv.y);
            }
        }
    }
    // bias + exact GELU -> y1s[p][perm(o)], tf32-rounded
    #pragma unroll
    for (int mt = 0; mt < 2; mt++) {
        #pragma unroll
        for (int nt = 0; nt < 4; nt++) {
            int col = n0 + nt * 8 + 2 * quad;
            int p0 = perm8(col), p1 = perm8(col + 1);
            float bb0 = b1[col], bb1 = b1[col + 1];
            int r = m0 + mt * 16 + row;
            float v0 = acc[mt][nt][0] + bb0;
            float v1 = acc[mt][nt][1] + bb1;
            float v2 = acc[mt][nt][2] + bb0;
            float v3 = acc[mt][nt][3] + bb1;
            y1s[r * 264 + p0]       = tfr(0.5f * v0 * (1.0f + erff(v0 * 0.70710678118654752f)));
            y1s[r * 264 + p1]       = tfr(0.5f * v1 * (1.0f + erff(v1 * 0.70710678118654752f)));
            y1s[(r + 8) * 264 + p0] = tfr(0.5f * v2 * (1.0f + erff(v2 * 0.70710678118654752f)));
            y1s[(r + 8) * 264 + p1] = tfr(0.5f * v3 * (1.0f + erff(v3 * 0.70710678118654752f)));
        }
    }
    __syncthreads();

    // ---- GEMM2: OUT(64x128) = Y1 @ W2^T : warp tile m16 x n32 ----
    int m0b = (warp & 3) * 16;
    int n0b = (warp >> 2) * 32;
    float ac2[4][4] = {};
    for (int it = 0; it < 4; it++) {
        for (int idx = tid; idx < 128 * 16; idx += 512) {
            int o = idx >> 4, kv = idx & 15;
            *(float4*)(wts + o * 72 + kv * 4) = *(const float4*)(g_w2p + (size_t)o * HID_ + it * 64 + kv * 4);
        }
        __syncthreads();
        #pragma unroll
        for (int kk = 0; kk < 8; kk++) {
            int kg = it * 64 + kk * 8;
            int kb = kk * 8;
            float2 aA = *(float2*)(y1s + (m0b + row) * 264 + kg + 2 * quad);
            float2 aB = *(float2*)(y1s + (m0b + row + 8) * 264 + kg + 2 * quad);
            #pragma unroll
            for (int nt = 0; nt < 4; nt++) {
                float2 bv = *(float2*)(wts + (n0b + nt * 8 + row) * 72 + kb + 2 * quad);
                mma_tf32(ac2[nt], aA.x, aB.x, aA.y, aB.y, bv.x, bv.y);
            }
        }
        __syncthreads();
    }

    // ---- epilogue: + b2, write (bs, o, l) ----
    float* og = out + (size_t)bs * OUTC_ * L_;
    int l = l0 + m0b + row;
    #pragma unroll
    for (int nt = 0; nt < 4; nt++) {
        int col = n0b + nt * 8 + 2 * quad;
        float bb0 = b2[col], bb1 = b2[col + 1];
        og[(size_t)col * L_ + l]           = ac2[nt][0] + bb0;
        og[(size_t)(col + 1) * L_ + l]     = ac2[nt][1] + bb1;
        og[(size_t)col * L_ + l + 8]       = ac2[nt][2] + bb0;
        og[(size_t)(col + 1) * L_ + l + 8] = ac2[nt][3] + bb1;
    }
}

// ---------------- launch ----------------
extern "C" void kernel_launch(void* const* d_in, const int* in_sizes, int n_in,
                              void* d_out, int out_size) {
    const float* x      = (const float*)d_in[0];
    const float* qk_w   = (const float*)d_in[1];
    const float* v_w    = (const float*)d_in[2];
    const float* cpb_w1 = (const float*)d_in[3];
    const float* cpb_b1 = (const float*)d_in[4];
    const float* cpb_w2 = (const float*)d_in[5];
    const float* sa_b   = (const float*)d_in[6];
    const float* mlp_b1 = (const float*)d_in[8];
    const float* mlp_b2 = (const float*)d_in[10];
    float* out = (float*)d_out;

    const int SMEM_QKV = (128 * 72 + 64 * 136 + 64 * 72) * 4;                  // 90112
    const int SMEM_ATT = (64 * 72 * 3 + 128 * 72 + 192) * 4;                   // 92928
    const int SMEM_MLP = (64 * 264 * 2 + 256 * 72) * 4;                        // 208896

    cudaFuncSetAttribute(qkv_kernel,  cudaFuncAttributeMaxDynamicSharedMemorySize, SMEM_QKV);
    cudaFuncSetAttribute(attn_kernel, cudaFuncAttributeMaxDynamicSharedMemorySize, SMEM_ATT);
    cudaFuncSetAttribute(mlp_kernel,  cudaFuncAttributeMaxDynamicSharedMemorySize, SMEM_MLP);

    prep_kernel<<<640, 256>>>(qk_w, v_w, (const float*)d_in[7], (const float*)d_in[9]);
    cpb_bias_kernel<<<(L_ * L_) / 256, 256>>>(cpb_w1, cpb_b1, cpb_w2);
    qkv_kernel<<<dim3(9, BS_), 256, SMEM_QKV>>>(x);
    attn_kernel<<<dim3(9, BS_ * HEADS_), 512, SMEM_ATT>>>(sa_b);
    mlp_kernel<<<BS_ * 9, 512, SMEM_MLP>>>(mlp_b1, mlp_b2, out);
}